// round 4
// baseline (speedup 1.0000x reference)
#include <cuda_runtime.h>
#include <cuda_bf16.h>
#include <math.h>
#include <stdint.h>

#define DMODEL 1024
#define DINNER 2048
#define DSTATE 16
#define SEQLEN 2048
#define NTOK   4096   /* BATCH * SEQLEN */

// ---------------- scratch (device globals; no runtime allocation) ----------------
__device__ __nv_bfloat16 g_xh [NTOK * DMODEL],  g_xl [NTOK * DMODEL];
__device__ __nv_bfloat16 g_wzh[DINNER * DMODEL], g_wzl[DINNER * DMODEL];
__device__ __nv_bfloat16 g_wth[DMODEL * DINNER], g_wtl[DMODEL * DINNER]; // WxcT
__device__ __nv_bfloat16 g_Ph [4u * DINNER * DINNER], g_Pl [4u * DINNER * DINNER];
__device__ float         g_Mf [4u * DINNER * DMODEL];
__device__ __nv_bfloat16 g_Mbh[DINNER * 4 * DMODEL], g_Mbl[DINNER * 4 * DMODEL];
__device__ __nv_bfloat16 g_dwh[DINNER * DINNER], g_dwl[DINNER * DINNER];
__device__ __nv_bfloat16 g_owh[DMODEL * DINNER], g_owl[DMODEL * DINNER];
__device__ float         g_u  [NTOK * DINNER];
__device__ __nv_bfloat16 g_uh [NTOK * DINNER], g_ul [NTOK * DINNER];
__device__ float         g_s  [NTOK * DINNER];       // silu(z)
__device__ float         g_dt [NTOK * DINNER];
__device__ __nv_bfloat16 g_yh [NTOK * DINNER], g_yl [NTOK * DINNER];
__device__ float         g_Bm [NTOK * DSTATE], g_Cm [NTOK * DSTATE];

// ---------------- helpers ----------------
__device__ __forceinline__ uint32_t smem_u32(const void* p) {
    uint32_t a;
    asm("{ .reg .u64 t; cvta.to.shared.u64 t, %1; cvt.u32.u64 %0, t; }" : "=r"(a) : "l"(p));
    return a;
}
__device__ __forceinline__ void split2(float v, __nv_bfloat16& h, __nv_bfloat16& l) {
    h = __float2bfloat16(v);
    l = __float2bfloat16(v - __bfloat162float(h));
}

#define LDSM4(r, a) asm volatile( \
    "ldmatrix.sync.aligned.m8n8.x4.shared.b16 {%0,%1,%2,%3}, [%4];" \
    : "=r"((r)[0]), "=r"((r)[1]), "=r"((r)[2]), "=r"((r)[3]) : "r"(a))

#define MMA16816(c, a, b0, b1) asm volatile( \
    "mma.sync.aligned.m16n8k16.row.col.f32.bf16.bf16.f32 " \
    "{%0,%1,%2,%3},{%4,%5,%6,%7},{%8,%9},{%0,%1,%2,%3};" \
    : "+f"((c)[0]), "+f"((c)[1]), "+f"((c)[2]), "+f"((c)[3]) \
    : "r"((a)[0]), "r"((a)[1]), "r"((a)[2]), "r"((a)[3]), "r"(b0), "r"(b1))

#define CPA(dst, src, sz) asm volatile( \
    "cp.async.cg.shared.global [%0], [%1], 16, %2;" :: "r"(dst), "l"(src), "r"(sz))

// ---------------- conversion kernels ----------------
__global__ void split_k(const float* __restrict__ in, __nv_bfloat16* __restrict__ h,
                        __nv_bfloat16* __restrict__ l) {
    int i = blockIdx.x * 256 + threadIdx.x;
    float4 v = reinterpret_cast<const float4*>(in)[i];
    float vv[4] = {v.x, v.y, v.z, v.w};
    __nv_bfloat16 hh[4], ll[4];
#pragma unroll
    for (int j = 0; j < 4; j++) split2(vv[j], hh[j], ll[j]);
    reinterpret_cast<__nv_bfloat162*>(h)[2 * i]     = __nv_bfloat162(hh[0], hh[1]);
    reinterpret_cast<__nv_bfloat162*>(h)[2 * i + 1] = __nv_bfloat162(hh[2], hh[3]);
    reinterpret_cast<__nv_bfloat162*>(l)[2 * i]     = __nv_bfloat162(ll[0], ll[1]);
    reinterpret_cast<__nv_bfloat162*>(l)[2 * i + 1] = __nv_bfloat162(ll[2], ll[3]);
}

// transpose-split: in_proj rows 0..2047 ([2048,1024]) -> WxcT [1024,2048]
__global__ void tsplit_k(const float* __restrict__ w, __nv_bfloat16* __restrict__ th,
                         __nv_bfloat16* __restrict__ tl) {
    __shared__ float t[32][33];
    int j0 = blockIdx.x * 32, i0 = blockIdx.y * 32;
    int tx = threadIdx.x & 31, ty4 = threadIdx.x >> 5;
#pragma unroll
    for (int s = 0; s < 4; s++) {
        int ty = ty4 + s * 8;
        t[ty][tx] = w[(size_t)(i0 + ty) * DMODEL + j0 + tx];
    }
    __syncthreads();
#pragma unroll
    for (int s = 0; s < 4; s++) {
        int ty = ty4 + s * 8;
        __nv_bfloat16 h, l;
        split2(t[tx][ty], h, l);
        th[(size_t)(j0 + ty) * DINNER + i0 + tx] = h;
        tl[(size_t)(j0 + ty) * DINNER + i0 + tx] = l;
    }
}

// Mf [(tap*2048+d), j] fp32 -> Mb[d][tap*1024+j] bf16 hi/lo
__global__ void mrelayout_k(const float* __restrict__ mf) {
    int g = blockIdx.x * 256 + threadIdx.x;
    int e = g * 4, row = e >> 10, j = e & 1023;
    int tap = row >> 11, d = row & 2047;
    float4 v = reinterpret_cast<const float4*>(mf)[g];
    float vv[4] = {v.x, v.y, v.z, v.w};
    size_t dst = (size_t)d * 4096 + tap * 1024 + j;
    __nv_bfloat16 hh[4], ll[4];
#pragma unroll
    for (int q = 0; q < 4; q++) split2(vv[q], hh[q], ll[q]);
    *reinterpret_cast<__nv_bfloat162*>(g_Mbh + dst)     = __nv_bfloat162(hh[0], hh[1]);
    *reinterpret_cast<__nv_bfloat162*>(g_Mbh + dst + 2) = __nv_bfloat162(hh[2], hh[3]);
    *reinterpret_cast<__nv_bfloat162*>(g_Mbl + dst)     = __nv_bfloat162(ll[0], ll[1]);
    *reinterpret_cast<__nv_bfloat162*>(g_Mbl + dst + 2) = __nv_bfloat162(ll[2], ll[3]);
}

// conv_w [d][i][4] -> P_hi/lo [tap][d][i]
__global__ void pack_split_k(const float* __restrict__ cw) {
    int g = blockIdx.x * 256 + threadIdx.x;
    float4 v = reinterpret_cast<const float4*>(cw)[g];
    float vv[4] = {v.x, v.y, v.z, v.w};
#pragma unroll
    for (int t = 0; t < 4; t++) {
        __nv_bfloat16 h, l;
        split2(vv[t], h, l);
        g_Ph[(size_t)t * 4194304u + g] = h;
        g_Pl[(size_t)t * 4194304u + g] = l;
    }
}

// ---------------- HMMA bf16x3 GEMM: D = A @ B^T (both operands K-major) ----------------
// MODE 0: normal. MODE 1: conv-fold (A = x with per-1024-K-chunk row shift tap-3).
// EPI 0: none, 1: silu, 2: sigmoid+clip. HASB: +bias[n]. HILO: also write bf16 hi/lo split.
#define KTILE   64
#define PITCH_B 144                // 64 halves data + 16B pad -> conflict-free ldmatrix
#define MATB    (128 * PITCH_B)    // 18432 B per matrix tile
#define STAGEB  (4 * MATB)         // Ah, Al, Bh, Bl = 73728 B
#define NSTAGE  3
#define GSMEM   (NSTAGE * STAGEB)  // 221184 B

template<int MODE, int EPI, bool HASB, bool HILO>
__global__ __launch_bounds__(256)
void tgemm(const __nv_bfloat16* __restrict__ Ah, const __nv_bfloat16* __restrict__ Al,
           const __nv_bfloat16* __restrict__ Bh, const __nv_bfloat16* __restrict__ Bl,
           const float* __restrict__ bias, float* __restrict__ out,
           __nv_bfloat16* __restrict__ oh, __nv_bfloat16* __restrict__ ol,
           int M, int N, int K)
{
    extern __shared__ char sm_[];
    const int tid = threadIdx.x, lane = tid & 31, wid = tid >> 5;
    const int m0 = blockIdx.y * 128, n0 = blockIdx.x * 128;
    const uint32_t sb = smem_u32(sm_);

    const int wm = wid >> 2, wn = wid & 3;          // warp tile: 64(m) x 32(n)
    const int lr = lane & 15, lc8 = (lane >> 4) * 8;
    const uint32_t aoffH = (uint32_t)((wm * 64 + lr) * PITCH_B + lc8 * 2);
    const uint32_t aoffL = aoffH + MATB;
    const uint32_t boffH = (uint32_t)(2 * MATB + (wn * 32 + lr) * PITCH_B + lc8 * 2);
    const uint32_t boffL = boffH + MATB;

    float acc[4][4][4] = {};

    // stage loader: 16 x 16B chunks per thread (4096 chunks total)
    auto ldst = [&](int kt) {
        const uint32_t st = sb + (kt % NSTAGE) * STAGEB;
        const int kb = kt * KTILE;
#pragma unroll
        for (int q = 0; q < 16; q++) {
            int cid = q * 256 + tid;
            int mat = cid >> 10, w = cid & 1023, row = w >> 3, c = w & 7;
            uint32_t dst = st + mat * MATB + row * PITCH_B + c * 16;
            const __nv_bfloat16* src;
            uint32_t sz = 16;
            if (mat < 2) {
                const __nv_bfloat16* base = mat ? Al : Ah;
                if (MODE == 1) {
                    int tap = kb >> 10, jb = kb & 1023, rg = m0 + row;
                    if (((rg & (SEQLEN - 1)) + tap - 3) < 0) { sz = 0; src = base; }
                    else src = base + (size_t)(rg + tap - 3) * DMODEL + jb + c * 8;
                } else {
                    src = base + (size_t)(m0 + row) * K + kb + c * 8;
                }
            } else {
                src = ((mat == 3) ? Bl : Bh) + (size_t)(n0 + row) * K + kb + c * 8;
            }
            CPA(dst, src, sz);
        }
        asm volatile("cp.async.commit_group;" ::: "memory");
    };

    auto comp = [&](int s) {
        const uint32_t st = sb + s * STAGEB;
#pragma unroll
        for (int kk = 0; kk < KTILE / 16; kk++) {
            const uint32_t ko = kk * 32;            // 16 halves = 32 bytes
            uint32_t ah[4][4], bhf[2][4], blf[2][4];
#pragma unroll
            for (int mt = 0; mt < 4; mt++) LDSM4(ah[mt], st + aoffH + mt * 16 * PITCH_B + ko);
#pragma unroll
            for (int np = 0; np < 2; np++) LDSM4(bhf[np], st + boffH + np * 16 * PITCH_B + ko);
#pragma unroll
            for (int mt = 0; mt < 4; mt++)
#pragma unroll
                for (int nt = 0; nt < 4; nt++)
                    MMA16816(acc[mt][nt], ah[mt], bhf[nt >> 1][nt & 1], bhf[nt >> 1][2 + (nt & 1)]);
#pragma unroll
            for (int np = 0; np < 2; np++) LDSM4(blf[np], st + boffL + np * 16 * PITCH_B + ko);
#pragma unroll
            for (int mt = 0; mt < 4; mt++)
#pragma unroll
                for (int nt = 0; nt < 4; nt++)
                    MMA16816(acc[mt][nt], ah[mt], blf[nt >> 1][nt & 1], blf[nt >> 1][2 + (nt & 1)]);
#pragma unroll
            for (int mt = 0; mt < 4; mt++) {
                uint32_t alf[4];
                LDSM4(alf, st + aoffL + mt * 16 * PITCH_B + ko);
#pragma unroll
                for (int nt = 0; nt < 4; nt++)
                    MMA16816(acc[mt][nt], alf, bhf[nt >> 1][nt & 1], bhf[nt >> 1][2 + (nt & 1)]);
            }
        }
    };

    const int nk = K / KTILE;
    // 3-stage pipeline: 2 tiles always in flight, one barrier per tile.
    ldst(0);
    ldst(1);
    for (int kt = 0; kt < nk; kt++) {
        if (kt + 1 < nk) asm volatile("cp.async.wait_group 1;" ::: "memory");
        else             asm volatile("cp.async.wait_group 0;" ::: "memory");
        __syncthreads();                 // all warps done with comp(kt-1); stage (kt+2)%3 free
        if (kt + 2 < nk) ldst(kt + 2);
        comp(kt % NSTAGE);
    }

    // epilogue from register accumulators
    const int g = lane >> 2, tg = lane & 3;
#pragma unroll
    for (int mt = 0; mt < 4; mt++) {
#pragma unroll
        for (int nt = 0; nt < 4; nt++) {
            const int col = n0 + wn * 32 + nt * 8 + tg * 2;
            float b0 = 0.f, b1 = 0.f;
            if (HASB) { b0 = bias[col]; b1 = bias[col + 1]; }
#pragma unroll
            for (int h = 0; h < 2; h++) {
                const int r = m0 + wm * 64 + mt * 16 + g + h * 8;
                float v0 = acc[mt][nt][2 * h + 0] + b0;
                float v1 = acc[mt][nt][2 * h + 1] + b1;
                if (EPI == 1) {
                    v0 = v0 / (1.f + __expf(-v0));
                    v1 = v1 / (1.f + __expf(-v1));
                } else if (EPI == 2) {
                    v0 = fminf(fmaxf(1.f / (1.f + __expf(-v0)), 1e-4f), 1.f);
                    v1 = fminf(fmaxf(1.f / (1.f + __expf(-v1)), 1e-4f), 1.f);
                }
                *reinterpret_cast<float2*>(out + (size_t)r * N + col) = make_float2(v0, v1);
                if (HILO) {
                    __nv_bfloat16 h0, l0, h1, l1;
                    split2(v0, h0, l0); split2(v1, h1, l1);
                    *reinterpret_cast<__nv_bfloat162*>(oh + (size_t)r * N + col) = __nv_bfloat162(h0, h1);
                    *reinterpret_cast<__nv_bfloat162*>(ol + (size_t)r * N + col) = __nv_bfloat162(l0, l1);
                }
            }
        }
    }
}

// ---------------- small B/C projection GEMM ----------------
__global__ __launch_bounds__(256)
void bc_gemm(const float* __restrict__ u, const float* __restrict__ Bw,
             const float* __restrict__ Cw)
{
    __shared__ float us[32][65];
    __shared__ float ws[32][65];
    const int tid  = threadIdx.x;
    const int row0 = blockIdx.x * 32;
    const int c  = tid & 31;
    const int rq = tid >> 5;
    float acc[4] = {0.f, 0.f, 0.f, 0.f};

    for (int kt = 0; kt < DINNER; kt += 64) {
        __syncthreads();
#pragma unroll
        for (int s = 0; s < 8; s++) {
            int e = tid + s * 256;
            int r = e >> 6, k = e & 63;
            us[r][k] = u[(size_t)(row0 + r) * DINNER + kt + k];
            ws[r][k] = (r < 16) ? Bw[r * DINNER + kt + k]
                                : Cw[(r - 16) * DINNER + kt + k];
        }
        __syncthreads();
#pragma unroll 8
        for (int k = 0; k < 64; k++) {
            float wv = ws[c][k];
#pragma unroll
            for (int i = 0; i < 4; i++)
                acc[i] = fmaf(us[rq * 4 + i][k], wv, acc[i]);
        }
    }
#pragma unroll
    for (int i = 0; i < 4; i++) {
        int row = row0 + rq * 4 + i;
        if (c < 16) g_Bm[(size_t)row * DSTATE + c]        = acc[i];
        else        g_Cm[(size_t)row * DSTATE + (c - 16)] = acc[i];
    }
}

// ---------------- selective scan (emits pre-split y for the out GEMM) ----------------
__global__ __launch_bounds__(512)
void scan_k(const float* __restrict__ u, const float* __restrict__ dt,
            const float* __restrict__ Bm, const float* __restrict__ Cm,
            const float* __restrict__ Alog, const float* __restrict__ Dp,
            const float* __restrict__ sz,
            __nv_bfloat16* __restrict__ yh, __nv_bfloat16* __restrict__ yl)
{
    const int tid = threadIdx.x;
    const int b   = blockIdx.x >> 6;
    const int d0  = (blockIdx.x & 63) * 32;
    const int dl  = tid >> 4;
    const int n   = tid & 15;
    const int d   = d0 + dl;
    const float Areg = -expf(Alog[d * DSTATE + n]);
    const float Dreg = Dp[d];
    const size_t rowbase = (size_t)b * SEQLEN;
    float state = 0.f;

    __shared__ float dt_s[2][32][32];
    __shared__ float u_s [2][32][32];
    __shared__ float sz_s[2][32][32];
    __shared__ float B_s [2][32][16];
    __shared__ float C_s [2][32][16];
    __shared__ float y_s [32][32];

    auto stage = [&](int buf, int l0) {
#pragma unroll
        for (int s = 0; s < 2; s++) {
            int e = tid + s * 512;
            int ll = e >> 5, dd = e & 31;
            size_t g = (rowbase + l0 + ll) * DINNER + d0 + dd;
            dt_s[buf][ll][dd] = dt[g];
            u_s [buf][ll][dd] = u[g];
            sz_s[buf][ll][dd] = sz[g];
        }
        {
            int ll = tid >> 4, nn = tid & 15;
            size_t g = (rowbase + l0 + ll) * DSTATE + nn;
            B_s[buf][ll][nn] = Bm[g];
            C_s[buf][ll][nn] = Cm[g];
        }
    };

    stage(0, 0);
    __syncthreads();
    int buf = 0;
    for (int t = 0; t < SEQLEN / 32; t++) {
        const int l0 = t * 32;
        if (t + 1 < SEQLEN / 32) stage(buf ^ 1, l0 + 32);
#pragma unroll 4
        for (int ll = 0; ll < 32; ll++) {
            float dtv = dt_s[buf][ll][dl];
            float uv  = u_s [buf][ll][dl];
            float Bn  = B_s [buf][ll][n];
            float Cn  = C_s [buf][ll][n];
            float arg = fminf(fmaxf(dtv * Areg, -5.f), 5.f);
            float dA  = __expf(arg);
            float dB  = dtv * uv * Bn;
            state = fmaf(dA, state, dB + 1e-6f);
            float v = state * Cn;
            v += __shfl_xor_sync(0xffffffffu, v, 8);
            v += __shfl_xor_sync(0xffffffffu, v, 4);
            v += __shfl_xor_sync(0xffffffffu, v, 2);
            v += __shfl_xor_sync(0xffffffffu, v, 1);
            if (n == 0) y_s[ll][dl] = v + Dreg * uv;
        }
        __syncthreads();
#pragma unroll
        for (int s = 0; s < 2; s++) {
            int e = tid + s * 512;
            int ll = e >> 5, dd = e & 31;
            size_t g = (rowbase + l0 + ll) * DINNER + d0 + dd;
            float v = y_s[ll][dd] * sz_s[buf][ll][dd];
            __nv_bfloat16 h, l;
            split2(v, h, l);
            yh[g] = h; yl[g] = l;
        }
        __syncthreads();
        buf ^= 1;
    }
}

// ---------------- launch ----------------
extern "C" void kernel_launch(void* const* d_in, const int* in_sizes, int n_in,
                              void* d_out, int out_size)
{
    (void)in_sizes; (void)n_in; (void)out_size;
    const float* x       = (const float*)d_in[0];
    const float* in_proj = (const float*)d_in[1];
    const float* conv_w  = (const float*)d_in[2];
    const float* conv_b  = (const float*)d_in[3];
    const float* dt_w    = (const float*)d_in[4];
    const float* dt_b    = (const float*)d_in[5];
    const float* A_log   = (const float*)d_in[6];
    const float* Dp      = (const float*)d_in[7];
    const float* B_w     = (const float*)d_in[8];
    const float* C_w     = (const float*)d_in[9];
    const float* out_w   = (const float*)d_in[10];
    float* out = (float*)d_out;

    auto ga = [](const void* sym) { void* p; cudaGetSymbolAddress(&p, sym); return p; };
    __nv_bfloat16* xh  = (__nv_bfloat16*)ga(g_xh);   __nv_bfloat16* xl  = (__nv_bfloat16*)ga(g_xl);
    __nv_bfloat16* wzh = (__nv_bfloat16*)ga(g_wzh);  __nv_bfloat16* wzl = (__nv_bfloat16*)ga(g_wzl);
    __nv_bfloat16* wth = (__nv_bfloat16*)ga(g_wth);  __nv_bfloat16* wtl = (__nv_bfloat16*)ga(g_wtl);
    __nv_bfloat16* Ph  = (__nv_bfloat16*)ga(g_Ph);   __nv_bfloat16* Pl  = (__nv_bfloat16*)ga(g_Pl);
    float*         Mf  = (float*)ga(g_Mf);
    __nv_bfloat16* Mbh = (__nv_bfloat16*)ga(g_Mbh);  __nv_bfloat16* Mbl = (__nv_bfloat16*)ga(g_Mbl);
    __nv_bfloat16* dwh = (__nv_bfloat16*)ga(g_dwh);  __nv_bfloat16* dwl = (__nv_bfloat16*)ga(g_dwl);
    __nv_bfloat16* owh = (__nv_bfloat16*)ga(g_owh);  __nv_bfloat16* owl = (__nv_bfloat16*)ga(g_owl);
    float* u  = (float*)ga(g_u);
    __nv_bfloat16* uh = (__nv_bfloat16*)ga(g_uh);    __nv_bfloat16* ul = (__nv_bfloat16*)ga(g_ul);
    float* s  = (float*)ga(g_s);
    float* dtp = (float*)ga(g_dt);
    __nv_bfloat16* yh = (__nv_bfloat16*)ga(g_yh);    __nv_bfloat16* yl = (__nv_bfloat16*)ga(g_yl);
    float* Bm = (float*)ga(g_Bm);
    float* Cm = (float*)ga(g_Cm);

    cudaFuncSetAttribute(tgemm<0,0,false,false>, cudaFuncAttributeMaxDynamicSharedMemorySize, GSMEM);
    cudaFuncSetAttribute(tgemm<0,1,false,false>, cudaFuncAttributeMaxDynamicSharedMemorySize, GSMEM);
    cudaFuncSetAttribute(tgemm<1,0,true,true>,   cudaFuncAttributeMaxDynamicSharedMemorySize, GSMEM);
    cudaFuncSetAttribute(tgemm<0,2,true,false>,  cudaFuncAttributeMaxDynamicSharedMemorySize, GSMEM);

    // conversions
    split_k<<<4096, 256>>>(x, xh, xl);                                   // x
    split_k<<<2048, 256>>>(in_proj + (size_t)DINNER * DMODEL, wzh, wzl); // Wz
    tsplit_k<<<dim3(32, 64), 256>>>(in_proj, wth, wtl);                  // WxcT
    split_k<<<4096, 256>>>(dt_w, dwh, dwl);                              // dt_w
    split_k<<<2048, 256>>>(out_w, owh, owl);                             // out_w
    pack_split_k<<<16384, 256>>>(conv_w);                                // conv taps

    // fold: M_k = P_k @ Wxc   (M=8192, N=1024, K=2048)
    tgemm<0,0,false,false><<<dim3(8, 64), 256, GSMEM>>>(
        Ph, Pl, wth, wtl, nullptr, Mf, nullptr, nullptr, 8192, 1024, 2048);
    mrelayout_k<<<8192, 256>>>(Mf);

    // silu(z) = silu(x @ Wz^T)
    tgemm<0,1,false,false><<<dim3(16, 32), 256, GSMEM>>>(
        xh, xl, wzh, wzl, nullptr, s, nullptr, nullptr, NTOK, DINNER, DMODEL);

    // u = conv fold (shifted K=4096) + conv_b, also emits hi/lo split
    tgemm<1,0,true,true><<<dim3(16, 32), 256, GSMEM>>>(
        xh, xl, Mbh, Mbl, conv_b, u, uh, ul, NTOK, DINNER, 4 * DMODEL);

    // dt = clip(sigmoid(u @ dt_w^T + dt_b))
    tgemm<0,2,true,false><<<dim3(16, 32), 256, GSMEM>>>(
        uh, ul, dwh, dwl, dt_b, dtp, nullptr, nullptr, NTOK, DINNER, DINNER);

    // B/C projections
    bc_gemm<<<NTOK / 32, 256>>>(u, B_w, C_w);

    // selective scan -> y (pre-split bf16 hi/lo)
    scan_k<<<128, 512>>>(u, dtp, Bm, Cm, A_log, Dp, s, yh, yl);

    // out = y @ out_w^T
    tgemm<0,0,false,false><<<dim3(8, 32), 256, GSMEM>>>(
        yh, yl, owh, owl, nullptr, out, nullptr, nullptr, NTOK, DMODEL, DINNER);
}

// round 5
// speedup vs baseline: 1.1198x; 1.1198x over previous
#include <cuda_runtime.h>
#include <cuda_fp16.h>
#include <math.h>
#include <stdint.h>

#define DMODEL 1024
#define DINNER 2048
#define DSTATE 16
#define SEQLEN 2048
#define NTOK   4096   /* BATCH * SEQLEN */

// ---------------- scratch (device globals; no runtime allocation) ----------------
__device__ __half g_xh [NTOK * DMODEL],  g_xl [NTOK * DMODEL];
__device__ __half g_wzh[DINNER * DMODEL], g_wzl[DINNER * DMODEL];
__device__ __half g_wth[DMODEL * DINNER], g_wtl[DMODEL * DINNER]; // WxcT
__device__ __half g_Ph [4u * DINNER * DINNER], g_Pl [4u * DINNER * DINNER];
__device__ float  g_Mf [4u * DINNER * DMODEL];
__device__ __half g_Mbh[DINNER * 4 * DMODEL], g_Mbl[DINNER * 4 * DMODEL];
__device__ __half g_dwh[DINNER * DINNER];
__device__ __half g_owh[DMODEL * DINNER], g_owl[DMODEL * DINNER];
__device__ float  g_u  [NTOK * DINNER];
__device__ __half g_uh [NTOK * DINNER];
__device__ float  g_s  [NTOK * DINNER];       // silu(z)
__device__ float  g_dt [NTOK * DINNER];
__device__ __half g_yh [NTOK * DINNER], g_yl [NTOK * DINNER];
__device__ float  g_Bm [NTOK * DSTATE], g_Cm [NTOK * DSTATE];

// ---------------- helpers ----------------
__device__ __forceinline__ uint32_t smem_u32(const void* p) {
    uint32_t a;
    asm("{ .reg .u64 t; cvta.to.shared.u64 t, %1; cvt.u32.u64 %0, t; }" : "=r"(a) : "l"(p));
    return a;
}
__device__ __forceinline__ void split2(float v, __half& h, __half& l) {
    h = __float2half_rn(v);
    l = __float2half_rn(v - __half2float(h));
}

#define LDSM4(r, a) asm volatile( \
    "ldmatrix.sync.aligned.m8n8.x4.shared.b16 {%0,%1,%2,%3}, [%4];" \
    : "=r"((r)[0]), "=r"((r)[1]), "=r"((r)[2]), "=r"((r)[3]) : "r"(a))

#define MMAF32(c, a, b0, b1) asm volatile( \
    "mma.sync.aligned.m16n8k16.row.col.f32.f16.f16.f32 " \
    "{%0,%1,%2,%3},{%4,%5,%6,%7},{%8,%9},{%0,%1,%2,%3};" \
    : "+f"((c)[0]), "+f"((c)[1]), "+f"((c)[2]), "+f"((c)[3]) \
    : "r"((a)[0]), "r"((a)[1]), "r"((a)[2]), "r"((a)[3]), "r"(b0), "r"(b1))

#define MMAF16(c, a, b0, b1) asm volatile( \
    "mma.sync.aligned.m16n8k16.row.col.f16.f16.f16.f16 " \
    "{%0,%1},{%2,%3,%4,%5},{%6,%7},{%0,%1};" \
    : "+r"((c)[0]), "+r"((c)[1]) \
    : "r"((a)[0]), "r"((a)[1]), "r"((a)[2]), "r"((a)[3]), "r"(b0), "r"(b1))

#define CPA(dst, src, sz) asm volatile( \
    "cp.async.cg.shared.global [%0], [%1], 16, %2;" :: "r"(dst), "l"(src), "r"(sz))

// ---------------- conversion kernels ----------------
__global__ void split_k(const float* __restrict__ in, __half* __restrict__ h,
                        __half* __restrict__ l) {
    int i = blockIdx.x * 256 + threadIdx.x;
    float4 v = reinterpret_cast<const float4*>(in)[i];
    float vv[4] = {v.x, v.y, v.z, v.w};
    __half hh[4], ll[4];
#pragma unroll
    for (int j = 0; j < 4; j++) split2(vv[j], hh[j], ll[j]);
    reinterpret_cast<__half2*>(h)[2 * i]     = __half2(hh[0], hh[1]);
    reinterpret_cast<__half2*>(h)[2 * i + 1] = __half2(hh[2], hh[3]);
    reinterpret_cast<__half2*>(l)[2 * i]     = __half2(ll[0], ll[1]);
    reinterpret_cast<__half2*>(l)[2 * i + 1] = __half2(ll[2], ll[3]);
}

// hi-only split (dt_w needs no lo slice)
__global__ void splith_k(const float* __restrict__ in, __half* __restrict__ h) {
    int i = blockIdx.x * 256 + threadIdx.x;
    float4 v = reinterpret_cast<const float4*>(in)[i];
    reinterpret_cast<__half2*>(h)[2 * i]     = __floats2half2_rn(v.x, v.y);
    reinterpret_cast<__half2*>(h)[2 * i + 1] = __floats2half2_rn(v.z, v.w);
}

// transpose-split: in_proj rows 0..2047 ([2048,1024]) -> WxcT [1024,2048]
__global__ void tsplit_k(const float* __restrict__ w, __half* __restrict__ th,
                         __half* __restrict__ tl) {
    __shared__ float t[32][33];
    int j0 = blockIdx.x * 32, i0 = blockIdx.y * 32;
    int tx = threadIdx.x & 31, ty4 = threadIdx.x >> 5;
#pragma unroll
    for (int s = 0; s < 4; s++) {
        int ty = ty4 + s * 8;
        t[ty][tx] = w[(size_t)(i0 + ty) * DMODEL + j0 + tx];
    }
    __syncthreads();
#pragma unroll
    for (int s = 0; s < 4; s++) {
        int ty = ty4 + s * 8;
        __half h, l;
        split2(t[tx][ty], h, l);
        th[(size_t)(j0 + ty) * DINNER + i0 + tx] = h;
        tl[(size_t)(j0 + ty) * DINNER + i0 + tx] = l;
    }
}

// Mf [(tap*2048+d), j] fp32 -> Mb[d][tap*1024+j] f16 hi/lo
__global__ void mrelayout_k(const float* __restrict__ mf) {
    int g = blockIdx.x * 256 + threadIdx.x;
    int e = g * 4, row = e >> 10, j = e & 1023;
    int tap = row >> 11, d = row & 2047;
    float4 v = reinterpret_cast<const float4*>(mf)[g];
    float vv[4] = {v.x, v.y, v.z, v.w};
    size_t dst = (size_t)d * 4096 + tap * 1024 + j;
    __half hh[4], ll[4];
#pragma unroll
    for (int q = 0; q < 4; q++) split2(vv[q], hh[q], ll[q]);
    *reinterpret_cast<__half2*>(g_Mbh + dst)     = __half2(hh[0], hh[1]);
    *reinterpret_cast<__half2*>(g_Mbh + dst + 2) = __half2(hh[2], hh[3]);
    *reinterpret_cast<__half2*>(g_Mbl + dst)     = __half2(ll[0], ll[1]);
    *reinterpret_cast<__half2*>(g_Mbl + dst + 2) = __half2(ll[2], ll[3]);
}

// conv_w [d][i][4] -> P_hi/lo [tap][d][i]
__global__ void pack_split_k(const float* __restrict__ cw) {
    int g = blockIdx.x * 256 + threadIdx.x;
    float4 v = reinterpret_cast<const float4*>(cw)[g];
    float vv[4] = {v.x, v.y, v.z, v.w};
#pragma unroll
    for (int t = 0; t < 4; t++) {
        __half h, l;
        split2(vv[t], h, l);
        g_Ph[(size_t)t * 4194304u + g] = h;
        g_Pl[(size_t)t * 4194304u + g] = l;
    }
}

// ---------------- HMMA f16-split GEMM: D = A @ B^T (both operands K-major) ----------------
// MODE 0: normal. MODE 1: conv-fold (A = x with per-1024-K-chunk row shift tap-3).
// EPI 0: none, 1: silu, 2: sigmoid+clip. HASB: +bias[n]. HILO: also write f16 hi of result.
// NPASS 3: ah*bh (f32 acc) + ah*bl + al*bh (f16 acc).  NPASS 1: ah*bh only.
#define KTILE   64
#define PITCH_B 144                // 64 halves data + 16B pad -> conflict-free ldmatrix
#define MATB    (128 * PITCH_B)    // 18432 B per matrix tile
#define STAGEB  (4 * MATB)         // Ah, Al, Bh, Bl = 73728 B
#define NSTAGE  3
#define GSMEM   (NSTAGE * STAGEB)  // 221184 B

template<int MODE, int EPI, bool HASB, bool HILO, int NPASS>
__global__ __launch_bounds__(256)
void tgemm(const __half* __restrict__ Ah, const __half* __restrict__ Al,
           const __half* __restrict__ Bh, const __half* __restrict__ Bl,
           const float* __restrict__ bias, float* __restrict__ out,
           __half* __restrict__ oh,
           int M, int N, int K)
{
    extern __shared__ char sm_[];
    const int tid = threadIdx.x, lane = tid & 31, wid = tid >> 5;
    const int m0 = blockIdx.y * 128, n0 = blockIdx.x * 128;
    const uint32_t sb = smem_u32(sm_);

    const int wm = wid >> 2, wn = wid & 3;          // warp tile: 64(m) x 32(n)
    const int lr = lane & 15, lc8 = (lane >> 4) * 8;
    const uint32_t aoffH = (uint32_t)((wm * 64 + lr) * PITCH_B + lc8 * 2);
    const uint32_t aoffL = aoffH + MATB;
    const uint32_t boffH = (uint32_t)(2 * MATB + (wn * 32 + lr) * PITCH_B + lc8 * 2);
    const uint32_t boffL = boffH + MATB;

    float acc[4][4][4] = {};
    uint32_t accl[4][4][2];
    if (NPASS == 3) {
#pragma unroll
        for (int i = 0; i < 4; i++)
#pragma unroll
            for (int j = 0; j < 4; j++) { accl[i][j][0] = 0u; accl[i][j][1] = 0u; }
    }

    // stage loader
    auto ldst = [&](int kt) {
        const uint32_t st = sb + (kt % NSTAGE) * STAGEB;
        const int kb = kt * KTILE;
        const int NCH = (NPASS == 3) ? 16 : 8;      // chunks per thread
#pragma unroll
        for (int q = 0; q < NCH; q++) {
            int cid = q * 256 + tid;
            int mat, w;
            if (NPASS == 3) { mat = cid >> 10; w = cid & 1023; }
            else            { mat = (cid >> 10) * 2; w = cid & 1023; }  // mats 0 (Ah), 2 (Bh)
            int row = w >> 3, c = w & 7;
            uint32_t dst = st + mat * MATB + row * PITCH_B + c * 16;
            const __half* src;
            uint32_t sz = 16;
            if (mat < 2) {
                const __half* base = mat ? Al : Ah;
                if (MODE == 1) {
                    int tap = kb >> 10, jb = kb & 1023, rg = m0 + row;
                    if (((rg & (SEQLEN - 1)) + tap - 3) < 0) { sz = 0; src = base; }
                    else src = base + (size_t)(rg + tap - 3) * DMODEL + jb + c * 8;
                } else {
                    src = base + (size_t)(m0 + row) * K + kb + c * 8;
                }
            } else {
                src = ((mat == 3) ? Bl : Bh) + (size_t)(n0 + row) * K + kb + c * 8;
            }
            CPA(dst, src, sz);
        }
        asm volatile("cp.async.commit_group;" ::: "memory");
    };

    auto comp = [&](int s) {
        const uint32_t st = sb + s * STAGEB;
#pragma unroll
        for (int kk = 0; kk < KTILE / 16; kk++) {
            const uint32_t ko = kk * 32;            // 16 halves = 32 bytes
            uint32_t ah[4][4], bhf[2][4];
#pragma unroll
            for (int mt = 0; mt < 4; mt++) LDSM4(ah[mt], st + aoffH + mt * 16 * PITCH_B + ko);
#pragma unroll
            for (int np = 0; np < 2; np++) LDSM4(bhf[np], st + boffH + np * 16 * PITCH_B + ko);
#pragma unroll
            for (int mt = 0; mt < 4; mt++)
#pragma unroll
                for (int nt = 0; nt < 4; nt++)
                    MMAF32(acc[mt][nt], ah[mt], bhf[nt >> 1][nt & 1], bhf[nt >> 1][2 + (nt & 1)]);
            if (NPASS == 3) {
                uint32_t blf[2][4];
#pragma unroll
                for (int np = 0; np < 2; np++) LDSM4(blf[np], st + boffL + np * 16 * PITCH_B + ko);
#pragma unroll
                for (int mt = 0; mt < 4; mt++)
#pragma unroll
                    for (int nt = 0; nt < 4; nt++)
                        MMAF16(accl[mt][nt], ah[mt], blf[nt >> 1][nt & 1], blf[nt >> 1][2 + (nt & 1)]);
#pragma unroll
                for (int mt = 0; mt < 4; mt++) {
                    uint32_t alf[4];
                    LDSM4(alf, st + aoffL + mt * 16 * PITCH_B + ko);
#pragma unroll
                    for (int nt = 0; nt < 4; nt++)
                        MMAF16(accl[mt][nt], alf, bhf[nt >> 1][nt & 1], bhf[nt >> 1][2 + (nt & 1)]);
                }
            }
        }
    };

    const int nk = K / KTILE;
    ldst(0);
    ldst(1);
    for (int kt = 0; kt < nk; kt++) {
        if (kt + 1 < nk) asm volatile("cp.async.wait_group 1;" ::: "memory");
        else             asm volatile("cp.async.wait_group 0;" ::: "memory");
        __syncthreads();
        if (kt + 2 < nk) ldst(kt + 2);
        comp(kt % NSTAGE);
    }

    // epilogue from register accumulators
    const int g = lane >> 2, tg = lane & 3;
#pragma unroll
    for (int mt = 0; mt < 4; mt++) {
#pragma unroll
        for (int nt = 0; nt < 4; nt++) {
            const int col = n0 + wn * 32 + nt * 8 + tg * 2;
            float b0 = 0.f, b1 = 0.f;
            if (HASB) { b0 = bias[col]; b1 = bias[col + 1]; }
            float lo[4] = {0.f, 0.f, 0.f, 0.f};
            if (NPASS == 3) {
                float2 p0 = __half22float2(*reinterpret_cast<__half2*>(&accl[mt][nt][0]));
                float2 p1 = __half22float2(*reinterpret_cast<__half2*>(&accl[mt][nt][1]));
                lo[0] = p0.x; lo[1] = p0.y; lo[2] = p1.x; lo[3] = p1.y;
            }
#pragma unroll
            for (int h = 0; h < 2; h++) {
                const int r = m0 + wm * 64 + mt * 16 + g + h * 8;
                float v0 = acc[mt][nt][2 * h + 0] + lo[2 * h + 0] + b0;
                float v1 = acc[mt][nt][2 * h + 1] + lo[2 * h + 1] + b1;
                if (EPI == 1) {
                    v0 = v0 / (1.f + __expf(-v0));
                    v1 = v1 / (1.f + __expf(-v1));
                } else if (EPI == 2) {
                    v0 = fminf(fmaxf(1.f / (1.f + __expf(-v0)), 1e-4f), 1.f);
                    v1 = fminf(fmaxf(1.f / (1.f + __expf(-v1)), 1e-4f), 1.f);
                }
                *reinterpret_cast<float2*>(out + (size_t)r * N + col) = make_float2(v0, v1);
                if (HILO) {
                    *reinterpret_cast<__half2*>(oh + (size_t)r * N + col) = __floats2half2_rn(v0, v1);
                }
            }
        }
    }
}

// ---------------- small B/C projection GEMM ----------------
__global__ __launch_bounds__(256)
void bc_gemm(const float* __restrict__ u, const float* __restrict__ Bw,
             const float* __restrict__ Cw)
{
    __shared__ float us[32][65];
    __shared__ float ws[32][65];
    const int tid  = threadIdx.x;
    const int row0 = blockIdx.x * 32;
    const int c  = tid & 31;
    const int rq = tid >> 5;
    float acc[4] = {0.f, 0.f, 0.f, 0.f};

    for (int kt = 0; kt < DINNER; kt += 64) {
        __syncthreads();
#pragma unroll
        for (int s = 0; s < 8; s++) {
            int e = tid + s * 256;
            int r = e >> 6, k = e & 63;
            us[r][k] = u[(size_t)(row0 + r) * DINNER + kt + k];
            ws[r][k] = (r < 16) ? Bw[r * DINNER + kt + k]
                                : Cw[(r - 16) * DINNER + kt + k];
        }
        __syncthreads();
#pragma unroll 8
        for (int k = 0; k < 64; k++) {
            float wv = ws[c][k];
#pragma unroll
            for (int i = 0; i < 4; i++)
                acc[i] = fmaf(us[rq * 4 + i][k], wv, acc[i]);
        }
    }
#pragma unroll
    for (int i = 0; i < 4; i++) {
        int row = row0 + rq * 4 + i;
        if (c < 16) g_Bm[(size_t)row * DSTATE + c]        = acc[i];
        else        g_Cm[(size_t)row * DSTATE + (c - 16)] = acc[i];
    }
}

// ---------------- selective scan (emits pre-split y for the out GEMM) ----------------
__global__ __launch_bounds__(512)
void scan_k(const float* __restrict__ u, const float* __restrict__ dt,
            const float* __restrict__ Bm, const float* __restrict__ Cm,
            const float* __restrict__ Alog, const float* __restrict__ Dp,
            const float* __restrict__ sz,
            __half* __restrict__ yh, __half* __restrict__ yl)
{
    const int tid = threadIdx.x;
    const int b   = blockIdx.x >> 6;
    const int d0  = (blockIdx.x & 63) * 32;
    const int dl  = tid >> 4;
    const int n   = tid & 15;
    const int d   = d0 + dl;
    const float Areg = -expf(Alog[d * DSTATE + n]);
    const float Dreg = Dp[d];
    const size_t rowbase = (size_t)b * SEQLEN;
    float state = 0.f;

    __shared__ float dt_s[2][32][32];
    __shared__ float u_s [2][32][32];
    __shared__ float sz_s[2][32][32];
    __shared__ float B_s [2][32][16];
    __shared__ float C_s [2][32][16];
    __shared__ float y_s [32][32];

    auto stage = [&](int buf, int l0) {
#pragma unroll
        for (int s = 0; s < 2; s++) {
            int e = tid + s * 512;
            int ll = e >> 5, dd = e & 31;
            size_t g = (rowbase + l0 + ll) * DINNER + d0 + dd;
            dt_s[buf][ll][dd] = dt[g];
            u_s [buf][ll][dd] = u[g];
            sz_s[buf][ll][dd] = sz[g];
        }
        {
            int ll = tid >> 4, nn = tid & 15;
            size_t g = (rowbase + l0 + ll) * DSTATE + nn;
            B_s[buf][ll][nn] = Bm[g];
            C_s[buf][ll][nn] = Cm[g];
        }
    };

    stage(0, 0);
    __syncthreads();
    int buf = 0;
    for (int t = 0; t < SEQLEN / 32; t++) {
        const int l0 = t * 32;
        if (t + 1 < SEQLEN / 32) stage(buf ^ 1, l0 + 32);
#pragma unroll 4
        for (int ll = 0; ll < 32; ll++) {
            float dtv = dt_s[buf][ll][dl];
            float uv  = u_s [buf][ll][dl];
            float Bn  = B_s [buf][ll][n];
            float Cn  = C_s [buf][ll][n];
            float arg = fminf(fmaxf(dtv * Areg, -5.f), 5.f);
            float dA  = __expf(arg);
            float dB  = dtv * uv * Bn;
            state = fmaf(dA, state, dB + 1e-6f);
            float v = state * Cn;
            v += __shfl_xor_sync(0xffffffffu, v, 8);
            v += __shfl_xor_sync(0xffffffffu, v, 4);
            v += __shfl_xor_sync(0xffffffffu, v, 2);
            v += __shfl_xor_sync(0xffffffffu, v, 1);
            if (n == 0) y_s[ll][dl] = v + Dreg * uv;
        }
        __syncthreads();
#pragma unroll
        for (int s = 0; s < 2; s++) {
            int e = tid + s * 512;
            int ll = e >> 5, dd = e & 31;
            size_t g = (rowbase + l0 + ll) * DINNER + d0 + dd;
            float v = y_s[ll][dd] * sz_s[buf][ll][dd];
            __half h, l;
            split2(v, h, l);
            yh[g] = h; yl[g] = l;
        }
        __syncthreads();
        buf ^= 1;
    }
}

// ---------------- launch ----------------
extern "C" void kernel_launch(void* const* d_in, const int* in_sizes, int n_in,
                              void* d_out, int out_size)
{
    (void)in_sizes; (void)n_in; (void)out_size;
    const float* x       = (const float*)d_in[0];
    const float* in_proj = (const float*)d_in[1];
    const float* conv_w  = (const float*)d_in[2];
    const float* conv_b  = (const float*)d_in[3];
    const float* dt_w    = (const float*)d_in[4];
    const float* dt_b    = (const float*)d_in[5];
    const float* A_log   = (const float*)d_in[6];
    const float* Dp      = (const float*)d_in[7];
    const float* B_w     = (const float*)d_in[8];
    const float* C_w     = (const float*)d_in[9];
    const float* out_w   = (const float*)d_in[10];
    float* out = (float*)d_out;

    auto ga = [](const void* sym) { void* p; cudaGetSymbolAddress(&p, sym); return p; };
    __half* xh  = (__half*)ga(g_xh);   __half* xl  = (__half*)ga(g_xl);
    __half* wzh = (__half*)ga(g_wzh);  __half* wzl = (__half*)ga(g_wzl);
    __half* wth = (__half*)ga(g_wth);  __half* wtl = (__half*)ga(g_wtl);
    __half* Ph  = (__half*)ga(g_Ph);   __half* Pl  = (__half*)ga(g_Pl);
    float*  Mf  = (float*)ga(g_Mf);
    __half* Mbh = (__half*)ga(g_Mbh);  __half* Mbl = (__half*)ga(g_Mbl);
    __half* dwh = (__half*)ga(g_dwh);
    __half* owh = (__half*)ga(g_owh);  __half* owl = (__half*)ga(g_owl);
    float* u  = (float*)ga(g_u);
    __half* uh = (__half*)ga(g_uh);
    float* s  = (float*)ga(g_s);
    float* dtp = (float*)ga(g_dt);
    __half* yh = (__half*)ga(g_yh);    __half* yl = (__half*)ga(g_yl);
    float* Bm = (float*)ga(g_Bm);
    float* Cm = (float*)ga(g_Cm);

    cudaFuncSetAttribute(tgemm<0,0,false,false,3>, cudaFuncAttributeMaxDynamicSharedMemorySize, GSMEM);
    cudaFuncSetAttribute(tgemm<0,1,false,false,3>, cudaFuncAttributeMaxDynamicSharedMemorySize, GSMEM);
    cudaFuncSetAttribute(tgemm<1,0,true,true,3>,   cudaFuncAttributeMaxDynamicSharedMemorySize, GSMEM);
    cudaFuncSetAttribute(tgemm<0,2,true,false,1>,  cudaFuncAttributeMaxDynamicSharedMemorySize, GSMEM);

    // conversions
    split_k<<<4096, 256>>>(x, xh, xl);                                   // x
    split_k<<<2048, 256>>>(in_proj + (size_t)DINNER * DMODEL, wzh, wzl); // Wz
    tsplit_k<<<dim3(32, 64), 256>>>(in_proj, wth, wtl);                  // WxcT
    splith_k<<<4096, 256>>>(dt_w, dwh);                                  // dt_w (hi only)
    split_k<<<2048, 256>>>(out_w, owh, owl);                             // out_w
    pack_split_k<<<16384, 256>>>(conv_w);                                // conv taps

    // fold: M_k = P_k @ Wxc   (M=8192, N=1024, K=2048)
    tgemm<0,0,false,false,3><<<dim3(8, 64), 256, GSMEM>>>(
        Ph, Pl, wth, wtl, nullptr, Mf, nullptr, 8192, 1024, 2048);
    mrelayout_k<<<8192, 256>>>(Mf);

    // silu(z) = silu(x @ Wz^T)
    tgemm<0,1,false,false,3><<<dim3(16, 32), 256, GSMEM>>>(
        xh, xl, wzh, wzl, nullptr, s, nullptr, NTOK, DINNER, DMODEL);

    // u = conv fold (shifted K=4096) + conv_b; also emits f16 hi of u
    tgemm<1,0,true,true,3><<<dim3(16, 32), 256, GSMEM>>>(
        xh, xl, Mbh, Mbl, conv_b, u, uh, NTOK, DINNER, 4 * DMODEL);

    // dt = clip(sigmoid(u @ dt_w^T + dt_b))  -- single-pass f16
    tgemm<0,2,true,false,1><<<dim3(16, 32), 256, GSMEM>>>(
        uh, nullptr, dwh, nullptr, dt_b, dtp, nullptr, NTOK, DINNER, DINNER);

    // B/C projections
    bc_gemm<<<NTOK / 32, 256>>>(u, B_w, C_w);

    // selective scan -> y (pre-split f16 hi/lo)
    scan_k<<<128, 512>>>(u, dtp, Bm, Cm, A_log, Dp, s, yh, yl);

    // out = y @ out_w^T
    tgemm<0,0,false,false,3><<<dim3(8, 32), 256, GSMEM>>>(
        yh, yl, owh, owl, nullptr, out, nullptr, NTOK, DMODEL, DINNER);
}

// round 6
// speedup vs baseline: 1.4143x; 1.2630x over previous
#include <cuda_runtime.h>
#include <cuda_fp16.h>
#include <math.h>
#include <stdint.h>

#define DMODEL 1024
#define DINNER 2048
#define DSTATE 16
#define SEQLEN 2048
#define NTOK   4096   /* BATCH * SEQLEN */

// ---------------- scratch (device globals; no runtime allocation) ----------------
__device__ __half g_xh [NTOK * DMODEL];
__device__ __half g_wzh[DINNER * DMODEL], g_wzl[DINNER * DMODEL];
__device__ __half g_wth[DMODEL * DINNER], g_wtl[DMODEL * DINNER]; // WxcT hi/lo
__device__ __half g_Ph [4u * DINNER * DINNER];
__device__ float  g_Mf [4u * DINNER * DMODEL];
__device__ __half g_Mbh[DINNER * 4 * DMODEL], g_Mbl[DINNER * 4 * DMODEL];
__device__ __half g_dwh[DINNER * DINNER];
__device__ __half g_owh[DMODEL * DINNER], g_owl[DMODEL * DINNER];
__device__ float  g_u  [NTOK * DINNER];
__device__ __half g_uh [NTOK * DINNER];
__device__ float  g_s  [NTOK * DINNER];       // silu(z)
__device__ float  g_dt [NTOK * DINNER];
__device__ __half g_yh [NTOK * DINNER];
__device__ float  g_Bm [NTOK * DSTATE], g_Cm [NTOK * DSTATE];

// ---------------- helpers ----------------
__device__ __forceinline__ uint32_t smem_u32(const void* p) {
    uint32_t a;
    asm("{ .reg .u64 t; cvta.to.shared.u64 t, %1; cvt.u32.u64 %0, t; }" : "=r"(a) : "l"(p));
    return a;
}
__device__ __forceinline__ void split2(float v, __half& h, __half& l) {
    h = __float2half_rn(v);
    l = __float2half_rn(v - __half2float(h));
}

#define LDSM4(r, a) asm volatile( \
    "ldmatrix.sync.aligned.m8n8.x4.shared.b16 {%0,%1,%2,%3}, [%4];" \
    : "=r"((r)[0]), "=r"((r)[1]), "=r"((r)[2]), "=r"((r)[3]) : "r"(a))

#define MMAF32(c, a, b0, b1) asm volatile( \
    "mma.sync.aligned.m16n8k16.row.col.f32.f16.f16.f32 " \
    "{%0,%1,%2,%3},{%4,%5,%6,%7},{%8,%9},{%0,%1,%2,%3};" \
    : "+f"((c)[0]), "+f"((c)[1]), "+f"((c)[2]), "+f"((c)[3]) \
    : "r"((a)[0]), "r"((a)[1]), "r"((a)[2]), "r"((a)[3]), "r"(b0), "r"(b1))

#define MMAF16(c, a, b0, b1) asm volatile( \
    "mma.sync.aligned.m16n8k16.row.col.f16.f16.f16.f16 " \
    "{%0,%1},{%2,%3,%4,%5},{%6,%7},{%0,%1};" \
    : "+r"((c)[0]), "+r"((c)[1]) \
    : "r"((a)[0]), "r"((a)[1]), "r"((a)[2]), "r"((a)[3]), "r"(b0), "r"(b1))

#define CPA(dst, src, sz) asm volatile( \
    "cp.async.cg.shared.global [%0], [%1], 16, %2;" :: "r"(dst), "l"(src), "r"(sz))

// ---------------- conversion kernels ----------------
__global__ void split_k(const float* __restrict__ in, __half* __restrict__ h,
                        __half* __restrict__ l) {
    int i = blockIdx.x * 256 + threadIdx.x;
    float4 v = reinterpret_cast<const float4*>(in)[i];
    float vv[4] = {v.x, v.y, v.z, v.w};
    __half hh[4], ll[4];
#pragma unroll
    for (int j = 0; j < 4; j++) split2(vv[j], hh[j], ll[j]);
    reinterpret_cast<__half2*>(h)[2 * i]     = __half2(hh[0], hh[1]);
    reinterpret_cast<__half2*>(h)[2 * i + 1] = __half2(hh[2], hh[3]);
    reinterpret_cast<__half2*>(l)[2 * i]     = __half2(ll[0], ll[1]);
    reinterpret_cast<__half2*>(l)[2 * i + 1] = __half2(ll[2], ll[3]);
}

// hi-only split
__global__ void splith_k(const float* __restrict__ in, __half* __restrict__ h) {
    int i = blockIdx.x * 256 + threadIdx.x;
    float4 v = reinterpret_cast<const float4*>(in)[i];
    reinterpret_cast<__half2*>(h)[2 * i]     = __floats2half2_rn(v.x, v.y);
    reinterpret_cast<__half2*>(h)[2 * i + 1] = __floats2half2_rn(v.z, v.w);
}

// transpose-split: in_proj rows 0..2047 ([2048,1024]) -> WxcT [1024,2048] hi/lo
__global__ void tsplit_k(const float* __restrict__ w, __half* __restrict__ th,
                         __half* __restrict__ tl) {
    __shared__ float t[32][33];
    int j0 = blockIdx.x * 32, i0 = blockIdx.y * 32;
    int tx = threadIdx.x & 31, ty4 = threadIdx.x >> 5;
#pragma unroll
    for (int s = 0; s < 4; s++) {
        int ty = ty4 + s * 8;
        t[ty][tx] = w[(size_t)(i0 + ty) * DMODEL + j0 + tx];
    }
    __syncthreads();
#pragma unroll
    for (int s = 0; s < 4; s++) {
        int ty = ty4 + s * 8;
        __half h, l;
        split2(t[tx][ty], h, l);
        th[(size_t)(j0 + ty) * DINNER + i0 + tx] = h;
        tl[(size_t)(j0 + ty) * DINNER + i0 + tx] = l;
    }
}

// Mf [(tap*2048+d), j] fp32 -> Mb[d][tap*1024+j] f16 hi/lo
__global__ void mrelayout_k(const float* __restrict__ mf) {
    int g = blockIdx.x * 256 + threadIdx.x;
    int e = g * 4, row = e >> 10, j = e & 1023;
    int tap = row >> 11, d = row & 2047;
    float4 v = reinterpret_cast<const float4*>(mf)[g];
    float vv[4] = {v.x, v.y, v.z, v.w};
    size_t dst = (size_t)d * 4096 + tap * 1024 + j;
    __half hh[4], ll[4];
#pragma unroll
    for (int q = 0; q < 4; q++) split2(vv[q], hh[q], ll[q]);
    *reinterpret_cast<__half2*>(g_Mbh + dst)     = __half2(hh[0], hh[1]);
    *reinterpret_cast<__half2*>(g_Mbh + dst + 2) = __half2(hh[2], hh[3]);
    *reinterpret_cast<__half2*>(g_Mbl + dst)     = __half2(ll[0], ll[1]);
    *reinterpret_cast<__half2*>(g_Mbl + dst + 2) = __half2(ll[2], ll[3]);
}

// conv_w [d][i][4] -> P_hi [tap][d][i]
__global__ void pack_split_k(const float* __restrict__ cw) {
    int g = blockIdx.x * 256 + threadIdx.x;
    float4 v = reinterpret_cast<const float4*>(cw)[g];
    float vv[4] = {v.x, v.y, v.z, v.w};
#pragma unroll
    for (int t = 0; t < 4; t++)
        g_Ph[(size_t)t * 4194304u + g] = __float2half_rn(vv[t]);
}

// ---------------- HMMA 2-pass GEMM: D = A @ B^T (both operands K-major) ----------------
// Passes: ah*bh (f32 acc) [+ ah*bl (f16 acc) if NPASS==2].  A-lo never used.
// MODE 0: normal. MODE 1: conv-fold (A = x with per-1024-K-chunk row shift tap-3).
// EPI 0: none, 1: silu, 2: sigmoid+clip. HASB: +bias[n]. HILO: also write f16 hi of result.
#define KTILE   64
#define PITCH_B 144                // 64 halves data + 16B pad -> conflict-free ldmatrix
#define MATB    (128 * PITCH_B)    // 18432 B per matrix tile
#define STAGEB  (3 * MATB)         // Ah, Bh, Bl = 55296 B
#define NSTAGE  3
#define GSMEM   (NSTAGE * STAGEB)  // 165888 B

template<int MODE, int EPI, bool HASB, bool HILO, int NPASS>
__global__ __launch_bounds__(256)
void tgemm(const __half* __restrict__ Ah,
           const __half* __restrict__ Bh, const __half* __restrict__ Bl,
           const float* __restrict__ bias, float* __restrict__ out,
           __half* __restrict__ oh,
           int M, int N, int K)
{
    extern __shared__ char sm_[];
    const int tid = threadIdx.x, lane = tid & 31, wid = tid >> 5;
    const int m0 = blockIdx.y * 128, n0 = blockIdx.x * 128;
    const uint32_t sb = smem_u32(sm_);

    const int wm = wid >> 2, wn = wid & 3;          // warp tile: 64(m) x 32(n)
    const int lr = lane & 15, lc8 = (lane >> 4) * 8;
    const uint32_t aoffH = (uint32_t)((wm * 64 + lr) * PITCH_B + lc8 * 2);
    const uint32_t boffH = (uint32_t)(MATB + (wn * 32 + lr) * PITCH_B + lc8 * 2);
    const uint32_t boffL = boffH + MATB;

    float acc[4][4][4] = {};
    uint32_t accl[4][4][2];
    if (NPASS == 2) {
#pragma unroll
        for (int i = 0; i < 4; i++)
#pragma unroll
            for (int j = 0; j < 4; j++) { accl[i][j][0] = 0u; accl[i][j][1] = 0u; }
    }

    // stage loader
    auto ldst = [&](int kt) {
        const uint32_t st = sb + (kt % NSTAGE) * STAGEB;
        const int kb = kt * KTILE;
        const int NCH = (NPASS == 2) ? 12 : 8;      // 16B chunks per thread
#pragma unroll
        for (int q = 0; q < NCH; q++) {
            int cid = q * 256 + tid;
            int mat = cid >> 10, w = cid & 1023;
            int row = w >> 3, c = w & 7;
            uint32_t dst = st + mat * MATB + row * PITCH_B + c * 16;
            const __half* src;
            uint32_t sz = 16;
            if (mat == 0) {
                if (MODE == 1) {
                    int tap = kb >> 10, jb = kb & 1023, rg = m0 + row;
                    if (((rg & (SEQLEN - 1)) + tap - 3) < 0) { sz = 0; src = Ah; }
                    else src = Ah + (size_t)(rg + tap - 3) * DMODEL + jb + c * 8;
                } else {
                    src = Ah + (size_t)(m0 + row) * K + kb + c * 8;
                }
            } else {
                src = ((mat == 2) ? Bl : Bh) + (size_t)(n0 + row) * K + kb + c * 8;
            }
            CPA(dst, src, sz);
        }
        asm volatile("cp.async.commit_group;" ::: "memory");
    };

    auto comp = [&](int s) {
        const uint32_t st = sb + s * STAGEB;
#pragma unroll
        for (int kk = 0; kk < KTILE / 16; kk++) {
            const uint32_t ko = kk * 32;            // 16 halves = 32 bytes
            uint32_t ah[4][4], bhf[2][4];
#pragma unroll
            for (int mt = 0; mt < 4; mt++) LDSM4(ah[mt], st + aoffH + mt * 16 * PITCH_B + ko);
#pragma unroll
            for (int np = 0; np < 2; np++) LDSM4(bhf[np], st + boffH + np * 16 * PITCH_B + ko);
#pragma unroll
            for (int mt = 0; mt < 4; mt++)
#pragma unroll
                for (int nt = 0; nt < 4; nt++)
                    MMAF32(acc[mt][nt], ah[mt], bhf[nt >> 1][nt & 1], bhf[nt >> 1][2 + (nt & 1)]);
            if (NPASS == 2) {
                uint32_t blf[2][4];
#pragma unroll
                for (int np = 0; np < 2; np++) LDSM4(blf[np], st + boffL + np * 16 * PITCH_B + ko);
#pragma unroll
                for (int mt = 0; mt < 4; mt++)
#pragma unroll
                    for (int nt = 0; nt < 4; nt++)
                        MMAF16(accl[mt][nt], ah[mt], blf[nt >> 1][nt & 1], blf[nt >> 1][2 + (nt & 1)]);
            }
        }
    };

    const int nk = K / KTILE;
    ldst(0);
    ldst(1);
    for (int kt = 0; kt < nk; kt++) {
        if (kt + 1 < nk) asm volatile("cp.async.wait_group 1;" ::: "memory");
        else             asm volatile("cp.async.wait_group 0;" ::: "memory");
        __syncthreads();
        if (kt + 2 < nk) ldst(kt + 2);
        comp(kt % NSTAGE);
    }

    // epilogue from register accumulators
    const int g = lane >> 2, tg = lane & 3;
#pragma unroll
    for (int mt = 0; mt < 4; mt++) {
#pragma unroll
        for (int nt = 0; nt < 4; nt++) {
            const int col = n0 + wn * 32 + nt * 8 + tg * 2;
            float b0 = 0.f, b1 = 0.f;
            if (HASB) { b0 = bias[col]; b1 = bias[col + 1]; }
            float lo[4] = {0.f, 0.f, 0.f, 0.f};
            if (NPASS == 2) {
                float2 p0 = __half22float2(*reinterpret_cast<__half2*>(&accl[mt][nt][0]));
                float2 p1 = __half22float2(*reinterpret_cast<__half2*>(&accl[mt][nt][1]));
                lo[0] = p0.x; lo[1] = p0.y; lo[2] = p1.x; lo[3] = p1.y;
            }
#pragma unroll
            for (int h = 0; h < 2; h++) {
                const int r = m0 + wm * 64 + mt * 16 + g + h * 8;
                float v0 = acc[mt][nt][2 * h + 0] + lo[2 * h + 0] + b0;
                float v1 = acc[mt][nt][2 * h + 1] + lo[2 * h + 1] + b1;
                if (EPI == 1) {
                    v0 = v0 / (1.f + __expf(-v0));
                    v1 = v1 / (1.f + __expf(-v1));
                } else if (EPI == 2) {
                    v0 = fminf(fmaxf(1.f / (1.f + __expf(-v0)), 1e-4f), 1.f);
                    v1 = fminf(fmaxf(1.f / (1.f + __expf(-v1)), 1e-4f), 1.f);
                }
                *reinterpret_cast<float2*>(out + (size_t)r * N + col) = make_float2(v0, v1);
                if (HILO) {
                    *reinterpret_cast<__half2*>(oh + (size_t)r * N + col) = __floats2half2_rn(v0, v1);
                }
            }
        }
    }
}

// ---------------- small B/C projection GEMM ----------------
__global__ __launch_bounds__(256)
void bc_gemm(const float* __restrict__ u, const float* __restrict__ Bw,
             const float* __restrict__ Cw)
{
    __shared__ float us[32][65];
    __shared__ float ws[32][65];
    const int tid  = threadIdx.x;
    const int row0 = blockIdx.x * 32;
    const int c  = tid & 31;
    const int rq = tid >> 5;
    float acc[4] = {0.f, 0.f, 0.f, 0.f};

    for (int kt = 0; kt < DINNER; kt += 64) {
        __syncthreads();
#pragma unroll
        for (int s = 0; s < 8; s++) {
            int e = tid + s * 256;
            int r = e >> 6, k = e & 63;
            us[r][k] = u[(size_t)(row0 + r) * DINNER + kt + k];
            ws[r][k] = (r < 16) ? Bw[r * DINNER + kt + k]
                                : Cw[(r - 16) * DINNER + kt + k];
        }
        __syncthreads();
#pragma unroll 8
        for (int k = 0; k < 64; k++) {
            float wv = ws[c][k];
#pragma unroll
            for (int i = 0; i < 4; i++)
                acc[i] = fmaf(us[rq * 4 + i][k], wv, acc[i]);
        }
    }
#pragma unroll
    for (int i = 0; i < 4; i++) {
        int row = row0 + rq * 4 + i;
        if (c < 16) g_Bm[(size_t)row * DSTATE + c]        = acc[i];
        else        g_Cm[(size_t)row * DSTATE + (c - 16)] = acc[i];
    }
}

// ---------------- selective scan (emits f16 hi of y for the out GEMM) ----------------
__global__ __launch_bounds__(512)
void scan_k(const float* __restrict__ u, const float* __restrict__ dt,
            const float* __restrict__ Bm, const float* __restrict__ Cm,
            const float* __restrict__ Alog, const float* __restrict__ Dp,
            const float* __restrict__ sz, __half* __restrict__ yh)
{
    const int tid = threadIdx.x;
    const int b   = blockIdx.x >> 6;
    const int d0  = (blockIdx.x & 63) * 32;
    const int dl  = tid >> 4;
    const int n   = tid & 15;
    const int d   = d0 + dl;
    const float Areg = -expf(Alog[d * DSTATE + n]);
    const float Dreg = Dp[d];
    const size_t rowbase = (size_t)b * SEQLEN;
    float state = 0.f;

    __shared__ float dt_s[2][32][32];
    __shared__ float u_s [2][32][32];
    __shared__ float sz_s[2][32][32];
    __shared__ float B_s [2][32][16];
    __shared__ float C_s [2][32][16];
    __shared__ float y_s [32][32];

    auto stage = [&](int buf, int l0) {
#pragma unroll
        for (int s = 0; s < 2; s++) {
            int e = tid + s * 512;
            int ll = e >> 5, dd = e & 31;
            size_t g = (rowbase + l0 + ll) * DINNER + d0 + dd;
            dt_s[buf][ll][dd] = dt[g];
            u_s [buf][ll][dd] = u[g];
            sz_s[buf][ll][dd] = sz[g];
        }
        {
            int ll = tid >> 4, nn = tid & 15;
            size_t g = (rowbase + l0 + ll) * DSTATE + nn;
            B_s[buf][ll][nn] = Bm[g];
            C_s[buf][ll][nn] = Cm[g];
        }
    };

    stage(0, 0);
    __syncthreads();
    int buf = 0;
    for (int t = 0; t < SEQLEN / 32; t++) {
        const int l0 = t * 32;
        if (t + 1 < SEQLEN / 32) stage(buf ^ 1, l0 + 32);
#pragma unroll 4
        for (int ll = 0; ll < 32; ll++) {
            float dtv = dt_s[buf][ll][dl];
            float uv  = u_s [buf][ll][dl];
            float Bn  = B_s [buf][ll][n];
            float Cn  = C_s [buf][ll][n];
            float arg = fminf(fmaxf(dtv * Areg, -5.f), 5.f);
            float dA  = __expf(arg);
            float dB  = dtv * uv * Bn;
            state = fmaf(dA, state, dB + 1e-6f);
            float v = state * Cn;
            v += __shfl_xor_sync(0xffffffffu, v, 8);
            v += __shfl_xor_sync(0xffffffffu, v, 4);
            v += __shfl_xor_sync(0xffffffffu, v, 2);
            v += __shfl_xor_sync(0xffffffffu, v, 1);
            if (n == 0) y_s[ll][dl] = v + Dreg * uv;
        }
        __syncthreads();
#pragma unroll
        for (int s = 0; s < 2; s++) {
            int e = tid + s * 512;
            int ll = e >> 5, dd = e & 31;
            size_t g = (rowbase + l0 + ll) * DINNER + d0 + dd;
            yh[g] = __float2half_rn(y_s[ll][dd] * sz_s[buf][ll][dd]);
        }
        __syncthreads();
        buf ^= 1;
    }
}

// ---------------- launch ----------------
extern "C" void kernel_launch(void* const* d_in, const int* in_sizes, int n_in,
                              void* d_out, int out_size)
{
    (void)in_sizes; (void)n_in; (void)out_size;
    const float* x       = (const float*)d_in[0];
    const float* in_proj = (const float*)d_in[1];
    const float* conv_w  = (const float*)d_in[2];
    const float* conv_b  = (const float*)d_in[3];
    const float* dt_w    = (const float*)d_in[4];
    const float* dt_b    = (const float*)d_in[5];
    const float* A_log   = (const float*)d_in[6];
    const float* Dp      = (const float*)d_in[7];
    const float* B_w     = (const float*)d_in[8];
    const float* C_w     = (const float*)d_in[9];
    const float* out_w   = (const float*)d_in[10];
    float* out = (float*)d_out;

    auto ga = [](const void* sym) { void* p; cudaGetSymbolAddress(&p, sym); return p; };
    __half* xh  = (__half*)ga(g_xh);
    __half* wzh = (__half*)ga(g_wzh);  __half* wzl = (__half*)ga(g_wzl);
    __half* wth = (__half*)ga(g_wth);  __half* wtl = (__half*)ga(g_wtl);
    __half* Ph  = (__half*)ga(g_Ph);
    float*  Mf  = (float*)ga(g_Mf);
    __half* Mbh = (__half*)ga(g_Mbh);  __half* Mbl = (__half*)ga(g_Mbl);
    __half* dwh = (__half*)ga(g_dwh);
    __half* owh = (__half*)ga(g_owh);  __half* owl = (__half*)ga(g_owl);
    float* u  = (float*)ga(g_u);
    __half* uh = (__half*)ga(g_uh);
    float* s  = (float*)ga(g_s);
    float* dtp = (float*)ga(g_dt);
    __half* yh = (__half*)ga(g_yh);
    float* Bm = (float*)ga(g_Bm);
    float* Cm = (float*)ga(g_Cm);

    cudaFuncSetAttribute(tgemm<0,0,false,false,2>, cudaFuncAttributeMaxDynamicSharedMemorySize, GSMEM);
    cudaFuncSetAttribute(tgemm<0,1,false,false,2>, cudaFuncAttributeMaxDynamicSharedMemorySize, GSMEM);
    cudaFuncSetAttribute(tgemm<1,0,true,true,2>,   cudaFuncAttributeMaxDynamicSharedMemorySize, GSMEM);
    cudaFuncSetAttribute(tgemm<0,2,true,false,1>,  cudaFuncAttributeMaxDynamicSharedMemorySize, GSMEM);

    // conversions
    splith_k<<<4096, 256>>>(x, xh);                                      // x (hi only)
    split_k<<<2048, 256>>>(in_proj + (size_t)DINNER * DMODEL, wzh, wzl); // Wz hi/lo
    tsplit_k<<<dim3(32, 64), 256>>>(in_proj, wth, wtl);                  // WxcT hi/lo
    splith_k<<<4096, 256>>>(dt_w, dwh);                                  // dt_w hi only
    split_k<<<2048, 256>>>(out_w, owh, owl);                             // out_w hi/lo
    pack_split_k<<<16384, 256>>>(conv_w);                                // conv taps hi only

    // fold: M_k = P_k @ Wxc   (M=8192, N=1024, K=2048), 2-pass
    tgemm<0,0,false,false,2><<<dim3(8, 64), 256, GSMEM>>>(
        Ph, wth, wtl, nullptr, Mf, nullptr, 8192, 1024, 2048);
    mrelayout_k<<<8192, 256>>>(Mf);

    // silu(z) = silu(x @ Wz^T), 2-pass
    tgemm<0,1,false,false,2><<<dim3(16, 32), 256, GSMEM>>>(
        xh, wzh, wzl, nullptr, s, nullptr, NTOK, DINNER, DMODEL);

    // u = conv fold (shifted K=4096) + conv_b; emits f16 hi of u; 2-pass
    tgemm<1,0,true,true,2><<<dim3(16, 32), 256, GSMEM>>>(
        xh, Mbh, Mbl, conv_b, u, uh, NTOK, DINNER, 4 * DMODEL);

    // dt = clip(sigmoid(u @ dt_w^T + dt_b)), 1-pass
    tgemm<0,2,true,false,1><<<dim3(16, 32), 256, GSMEM>>>(
        uh, dwh, nullptr, dt_b, dtp, nullptr, NTOK, DINNER, DINNER);

    // B/C projections
    bc_gemm<<<NTOK / 32, 256>>>(u, B_w, C_w);

    // selective scan -> yh (f16)
    scan_k<<<128, 512>>>(u, dtp, Bm, Cm, A_log, Dp, s, yh);

    // out = y @ out_w^T, 2-pass
    tgemm<0,0,false,false,2><<<dim3(8, 32), 256, GSMEM>>>(
        yh, owh, owl, nullptr, out, nullptr, NTOK, DMODEL, DINNER);
}

// round 7
// speedup vs baseline: 1.7360x; 1.2275x over previous
#include <cuda_runtime.h>
#include <cuda_fp16.h>
#include <math.h>
#include <stdint.h>

#define DMODEL 1024
#define DINNER 2048
#define DSTATE 16
#define SEQLEN 2048
#define NTOK   4096   /* BATCH * SEQLEN */

// ---------------- scratch (device globals; no runtime allocation) ----------------
__device__ __half g_xh [NTOK * DMODEL];
__device__ __half g_wzh[DINNER * DMODEL];
__device__ __half g_wth[DMODEL * DINNER];     // WxcT hi
__device__ __half g_Ph [4u * DINNER * DINNER];
__device__ float  g_Mf [4u * DINNER * DMODEL];
__device__ __half g_Mbh[DINNER * 4 * DMODEL], g_Mbl[DINNER * 4 * DMODEL];
__device__ __half g_dwh[DINNER * DINNER];
__device__ __half g_owh[DMODEL * DINNER];
__device__ float  g_u  [NTOK * DINNER];
__device__ __half g_uh [NTOK * DINNER];
__device__ float  g_s  [NTOK * DINNER];       // silu(z)
__device__ float  g_dt [NTOK * DINNER];
__device__ __half g_yh [NTOK * DINNER];
__device__ float  g_Bm [NTOK * DSTATE], g_Cm [NTOK * DSTATE];

// ---------------- helpers ----------------
__device__ __forceinline__ uint32_t smem_u32(const void* p) {
    uint32_t a;
    asm("{ .reg .u64 t; cvta.to.shared.u64 t, %1; cvt.u32.u64 %0, t; }" : "=r"(a) : "l"(p));
    return a;
}
__device__ __forceinline__ void split2(float v, __half& h, __half& l) {
    h = __float2half_rn(v);
    l = __float2half_rn(v - __half2float(h));
}

#define LDSM4(r, a) asm volatile( \
    "ldmatrix.sync.aligned.m8n8.x4.shared.b16 {%0,%1,%2,%3}, [%4];" \
    : "=r"((r)[0]), "=r"((r)[1]), "=r"((r)[2]), "=r"((r)[3]) : "r"(a))

#define MMAF32(c, a, b0, b1) asm volatile( \
    "mma.sync.aligned.m16n8k16.row.col.f32.f16.f16.f32 " \
    "{%0,%1,%2,%3},{%4,%5,%6,%7},{%8,%9},{%0,%1,%2,%3};" \
    : "+f"((c)[0]), "+f"((c)[1]), "+f"((c)[2]), "+f"((c)[3]) \
    : "r"((a)[0]), "r"((a)[1]), "r"((a)[2]), "r"((a)[3]), "r"(b0), "r"(b1))

#define MMAF16(c, a, b0, b1) asm volatile( \
    "mma.sync.aligned.m16n8k16.row.col.f16.f16.f16.f16 " \
    "{%0,%1},{%2,%3,%4,%5},{%6,%7},{%0,%1};" \
    : "+r"((c)[0]), "+r"((c)[1]) \
    : "r"((a)[0]), "r"((a)[1]), "r"((a)[2]), "r"((a)[3]), "r"(b0), "r"(b1))

#define CPA(dst, src, sz) asm volatile( \
    "cp.async.cg.shared.global [%0], [%1], 16, %2;" :: "r"(dst), "l"(src), "r"(sz))

// ---------------- conversion kernels ----------------
__global__ void split_k(const float* __restrict__ in, __half* __restrict__ h,
                        __half* __restrict__ l) {
    int i = blockIdx.x * 256 + threadIdx.x;
    float4 v = reinterpret_cast<const float4*>(in)[i];
    float vv[4] = {v.x, v.y, v.z, v.w};
    __half hh[4], ll[4];
#pragma unroll
    for (int j = 0; j < 4; j++) split2(vv[j], hh[j], ll[j]);
    reinterpret_cast<__half2*>(h)[2 * i]     = __half2(hh[0], hh[1]);
    reinterpret_cast<__half2*>(h)[2 * i + 1] = __half2(hh[2], hh[3]);
    reinterpret_cast<__half2*>(l)[2 * i]     = __half2(ll[0], ll[1]);
    reinterpret_cast<__half2*>(l)[2 * i + 1] = __half2(ll[2], ll[3]);
}

// hi-only split
__global__ void splith_k(const float* __restrict__ in, __half* __restrict__ h) {
    int i = blockIdx.x * 256 + threadIdx.x;
    float4 v = reinterpret_cast<const float4*>(in)[i];
    reinterpret_cast<__half2*>(h)[2 * i]     = __floats2half2_rn(v.x, v.y);
    reinterpret_cast<__half2*>(h)[2 * i + 1] = __floats2half2_rn(v.z, v.w);
}

// transpose hi: in_proj rows 0..2047 ([2048,1024]) -> WxcT [1024,2048]
__global__ void tsplit_k(const float* __restrict__ w, __half* __restrict__ th) {
    __shared__ float t[32][33];
    int j0 = blockIdx.x * 32, i0 = blockIdx.y * 32;
    int tx = threadIdx.x & 31, ty4 = threadIdx.x >> 5;
#pragma unroll
    for (int s = 0; s < 4; s++) {
        int ty = ty4 + s * 8;
        t[ty][tx] = w[(size_t)(i0 + ty) * DMODEL + j0 + tx];
    }
    __syncthreads();
#pragma unroll
    for (int s = 0; s < 4; s++) {
        int ty = ty4 + s * 8;
        th[(size_t)(j0 + ty) * DINNER + i0 + tx] = __float2half_rn(t[tx][ty]);
    }
}

// Mf [(tap*2048+d), j] fp32 -> Mb[d][tap*1024+j] f16 hi/lo
__global__ void mrelayout_k(const float* __restrict__ mf) {
    int g = blockIdx.x * 256 + threadIdx.x;
    int e = g * 4, row = e >> 10, j = e & 1023;
    int tap = row >> 11, d = row & 2047;
    float4 v = reinterpret_cast<const float4*>(mf)[g];
    float vv[4] = {v.x, v.y, v.z, v.w};
    size_t dst = (size_t)d * 4096 + tap * 1024 + j;
    __half hh[4], ll[4];
#pragma unroll
    for (int q = 0; q < 4; q++) split2(vv[q], hh[q], ll[q]);
    *reinterpret_cast<__half2*>(g_Mbh + dst)     = __half2(hh[0], hh[1]);
    *reinterpret_cast<__half2*>(g_Mbh + dst + 2) = __half2(hh[2], hh[3]);
    *reinterpret_cast<__half2*>(g_Mbl + dst)     = __half2(ll[0], ll[1]);
    *reinterpret_cast<__half2*>(g_Mbl + dst + 2) = __half2(ll[2], ll[3]);
}

// conv_w [d][i][4] -> P_hi [tap][d][i]
__global__ void pack_split_k(const float* __restrict__ cw) {
    int g = blockIdx.x * 256 + threadIdx.x;
    float4 v = reinterpret_cast<const float4*>(cw)[g];
    float vv[4] = {v.x, v.y, v.z, v.w};
#pragma unroll
    for (int t = 0; t < 4; t++)
        g_Ph[(size_t)t * 4194304u + g] = __float2half_rn(vv[t]);
}

// ---------------- HMMA GEMM: D = A @ B^T (both operands K-major) ----------------
// Passes: ah*bh (f32 acc) [+ ah*bl (f16 acc) if NPASS==2].
// MODE 0: normal. MODE 1: conv-fold (A = x with per-1024-K-chunk row shift tap-3).
// EPI 0: none, 1: silu, 2: sigmoid+clip. HASB: +bias[n]. HILO: also write f16 hi of result.
#define KTILE   64
#define PITCH_B 144                // 64 halves data + 16B pad -> conflict-free ldmatrix
#define MATB    (128 * PITCH_B)    // 18432 B per matrix tile
#define NSTAGE  3
#define GSMEM1  (NSTAGE * 2 * MATB)   // 110592 B (Ah, Bh)
#define GSMEM2  (NSTAGE * 3 * MATB)   // 165888 B (Ah, Bh, Bl)

template<int MODE, int EPI, bool HASB, bool HILO, int NPASS>
__global__ __launch_bounds__(256, (NPASS == 1) ? 2 : 1)
void tgemm(const __half* __restrict__ Ah,
           const __half* __restrict__ Bh, const __half* __restrict__ Bl,
           const float* __restrict__ bias, float* __restrict__ out,
           __half* __restrict__ oh,
           int M, int N, int K)
{
    constexpr int NMAT   = NPASS + 1;
    constexpr int STAGEB = NMAT * MATB;

    extern __shared__ char sm_[];
    const int tid = threadIdx.x, lane = tid & 31, wid = tid >> 5;
    const int m0 = blockIdx.y * 128, n0 = blockIdx.x * 128;
    const uint32_t sb = smem_u32(sm_);

    const int wm = wid >> 2, wn = wid & 3;          // warp tile: 64(m) x 32(n)
    const int lr = lane & 15, lc8 = (lane >> 4) * 8;
    const uint32_t aoffH = (uint32_t)((wm * 64 + lr) * PITCH_B + lc8 * 2);
    const uint32_t boffH = (uint32_t)(MATB + (wn * 32 + lr) * PITCH_B + lc8 * 2);
    const uint32_t boffL = boffH + MATB;

    float acc[4][4][4] = {};
    uint32_t accl[4][4][2];
    if (NPASS == 2) {
#pragma unroll
        for (int i = 0; i < 4; i++)
#pragma unroll
            for (int j = 0; j < 4; j++) { accl[i][j][0] = 0u; accl[i][j][1] = 0u; }
    }

    // stage loader
    auto ldst = [&](int kt) {
        const uint32_t st = sb + (kt % NSTAGE) * STAGEB;
        const int kb = kt * KTILE;
        const int NCH = NMAT * 4;                   // 16B chunks per thread
#pragma unroll
        for (int q = 0; q < NCH; q++) {
            int cid = q * 256 + tid;
            int mat = cid >> 10, w = cid & 1023;
            int row = w >> 3, c = w & 7;
            uint32_t dst = st + mat * MATB + row * PITCH_B + c * 16;
            const __half* src;
            uint32_t sz = 16;
            if (mat == 0) {
                if (MODE == 1) {
                    int tap = kb >> 10, jb = kb & 1023, rg = m0 + row;
                    if (((rg & (SEQLEN - 1)) + tap - 3) < 0) { sz = 0; src = Ah; }
                    else src = Ah + (size_t)(rg + tap - 3) * DMODEL + jb + c * 8;
                } else {
                    src = Ah + (size_t)(m0 + row) * K + kb + c * 8;
                }
            } else {
                src = ((mat == 2) ? Bl : Bh) + (size_t)(n0 + row) * K + kb + c * 8;
            }
            CPA(dst, src, sz);
        }
        asm volatile("cp.async.commit_group;" ::: "memory");
    };

    auto comp = [&](int s) {
        const uint32_t st = sb + s * STAGEB;
#pragma unroll
        for (int kk = 0; kk < KTILE / 16; kk++) {
            const uint32_t ko = kk * 32;            // 16 halves = 32 bytes
            uint32_t ah[4][4], bhf[2][4];
#pragma unroll
            for (int mt = 0; mt < 4; mt++) LDSM4(ah[mt], st + aoffH + mt * 16 * PITCH_B + ko);
#pragma unroll
            for (int np = 0; np < 2; np++) LDSM4(bhf[np], st + boffH + np * 16 * PITCH_B + ko);
#pragma unroll
            for (int mt = 0; mt < 4; mt++)
#pragma unroll
                for (int nt = 0; nt < 4; nt++)
                    MMAF32(acc[mt][nt], ah[mt], bhf[nt >> 1][nt & 1], bhf[nt >> 1][2 + (nt & 1)]);
            if (NPASS == 2) {
                uint32_t blf[2][4];
#pragma unroll
                for (int np = 0; np < 2; np++) LDSM4(blf[np], st + boffL + np * 16 * PITCH_B + ko);
#pragma unroll
                for (int mt = 0; mt < 4; mt++)
#pragma unroll
                    for (int nt = 0; nt < 4; nt++)
                        MMAF16(accl[mt][nt], ah[mt], blf[nt >> 1][nt & 1], blf[nt >> 1][2 + (nt & 1)]);
            }
        }
    };

    const int nk = K / KTILE;
    ldst(0);
    ldst(1);
    for (int kt = 0; kt < nk; kt++) {
        if (kt + 1 < nk) asm volatile("cp.async.wait_group 1;" ::: "memory");
        else             asm volatile("cp.async.wait_group 0;" ::: "memory");
        __syncthreads();
        if (kt + 2 < nk) ldst(kt + 2);
        comp(kt % NSTAGE);
    }

    // epilogue from register accumulators
    const int g = lane >> 2, tg = lane & 3;
#pragma unroll
    for (int mt = 0; mt < 4; mt++) {
#pragma unroll
        for (int nt = 0; nt < 4; nt++) {
            const int col = n0 + wn * 32 + nt * 8 + tg * 2;
            float b0 = 0.f, b1 = 0.f;
            if (HASB) { b0 = bias[col]; b1 = bias[col + 1]; }
            float lo[4] = {0.f, 0.f, 0.f, 0.f};
            if (NPASS == 2) {
                float2 p0 = __half22float2(*reinterpret_cast<__half2*>(&accl[mt][nt][0]));
                float2 p1 = __half22float2(*reinterpret_cast<__half2*>(&accl[mt][nt][1]));
                lo[0] = p0.x; lo[1] = p0.y; lo[2] = p1.x; lo[3] = p1.y;
            }
#pragma unroll
            for (int h = 0; h < 2; h++) {
                const int r = m0 + wm * 64 + mt * 16 + g + h * 8;
                float v0 = acc[mt][nt][2 * h + 0] + lo[2 * h + 0] + b0;
                float v1 = acc[mt][nt][2 * h + 1] + lo[2 * h + 1] + b1;
                if (EPI == 1) {
                    v0 = v0 / (1.f + __expf(-v0));
                    v1 = v1 / (1.f + __expf(-v1));
                } else if (EPI == 2) {
                    v0 = fminf(fmaxf(1.f / (1.f + __expf(-v0)), 1e-4f), 1.f);
                    v1 = fminf(fmaxf(1.f / (1.f + __expf(-v1)), 1e-4f), 1.f);
                }
                *reinterpret_cast<float2*>(out + (size_t)r * N + col) = make_float2(v0, v1);
                if (HILO) {
                    *reinterpret_cast<__half2*>(oh + (size_t)r * N + col) = __floats2half2_rn(v0, v1);
                }
            }
        }
    }
}

// ---------------- small B/C projection GEMM ----------------
__global__ __launch_bounds__(256)
void bc_gemm(const float* __restrict__ u, const float* __restrict__ Bw,
             const float* __restrict__ Cw)
{
    __shared__ float us[32][65];
    __shared__ float ws[32][65];
    const int tid  = threadIdx.x;
    const int row0 = blockIdx.x * 32;
    const int c  = tid & 31;
    const int rq = tid >> 5;
    float acc[4] = {0.f, 0.f, 0.f, 0.f};

    for (int kt = 0; kt < DINNER; kt += 64) {
        __syncthreads();
#pragma unroll
        for (int s = 0; s < 8; s++) {
            int e = tid + s * 256;
            int r = e >> 6, k = e & 63;
            us[r][k] = u[(size_t)(row0 + r) * DINNER + kt + k];
            ws[r][k] = (r < 16) ? Bw[r * DINNER + kt + k]
                                : Cw[(r - 16) * DINNER + kt + k];
        }
        __syncthreads();
#pragma unroll 8
        for (int k = 0; k < 64; k++) {
            float wv = ws[c][k];
#pragma unroll
            for (int i = 0; i < 4; i++)
                acc[i] = fmaf(us[rq * 4 + i][k], wv, acc[i]);
        }
    }
#pragma unroll
    for (int i = 0; i < 4; i++) {
        int row = row0 + rq * 4 + i;
        if (c < 16) g_Bm[(size_t)row * DSTATE + c]        = acc[i];
        else        g_Cm[(size_t)row * DSTATE + (c - 16)] = acc[i];
    }
}

// ---------------- selective scan (emits f16 hi of y for the out GEMM) ----------------
__global__ __launch_bounds__(512)
void scan_k(const float* __restrict__ u, const float* __restrict__ dt,
            const float* __restrict__ Bm, const float* __restrict__ Cm,
            const float* __restrict__ Alog, const float* __restrict__ Dp,
            const float* __restrict__ sz, __half* __restrict__ yh)
{
    const int tid = threadIdx.x;
    const int b   = blockIdx.x >> 6;
    const int d0  = (blockIdx.x & 63) * 32;
    const int dl  = tid >> 4;
    const int n   = tid & 15;
    const int d   = d0 + dl;
    const float Areg = -expf(Alog[d * DSTATE + n]);
    const float Dreg = Dp[d];
    const size_t rowbase = (size_t)b * SEQLEN;
    float state = 0.f;

    __shared__ float dt_s[2][32][32];
    __shared__ float u_s [2][32][32];
    __shared__ float sz_s[2][32][32];
    __shared__ float B_s [2][32][16];
    __shared__ float C_s [2][32][16];
    __shared__ float y_s [32][32];

    auto stage = [&](int buf, int l0) {
#pragma unroll
        for (int s = 0; s < 2; s++) {
            int e = tid + s * 512;
            int ll = e >> 5, dd = e & 31;
            size_t g = (rowbase + l0 + ll) * DINNER + d0 + dd;
            dt_s[buf][ll][dd] = dt[g];
            u_s [buf][ll][dd] = u[g];
            sz_s[buf][ll][dd] = sz[g];
        }
        {
            int ll = tid >> 4, nn = tid & 15;
            size_t g = (rowbase + l0 + ll) * DSTATE + nn;
            B_s[buf][ll][nn] = Bm[g];
            C_s[buf][ll][nn] = Cm[g];
        }
    };

    stage(0, 0);
    __syncthreads();
    int buf = 0;
    for (int t = 0; t < SEQLEN / 32; t++) {
        const int l0 = t * 32;
        if (t + 1 < SEQLEN / 32) stage(buf ^ 1, l0 + 32);
#pragma unroll 4
        for (int ll = 0; ll < 32; ll++) {
            float dtv = dt_s[buf][ll][dl];
            float uv  = u_s [buf][ll][dl];
            float Bn  = B_s [buf][ll][n];
            float Cn  = C_s [buf][ll][n];
            float arg = fminf(fmaxf(dtv * Areg, -5.f), 5.f);
            float dA  = __expf(arg);
            float dB  = dtv * uv * Bn;
            state = fmaf(dA, state, dB + 1e-6f);
            float v = state * Cn;
            v += __shfl_xor_sync(0xffffffffu, v, 8);
            v += __shfl_xor_sync(0xffffffffu, v, 4);
            v += __shfl_xor_sync(0xffffffffu, v, 2);
            v += __shfl_xor_sync(0xffffffffu, v, 1);
            if (n == 0) y_s[ll][dl] = v + Dreg * uv;
        }
        __syncthreads();
#pragma unroll
        for (int s = 0; s < 2; s++) {
            int e = tid + s * 512;
            int ll = e >> 5, dd = e & 31;
            size_t g = (rowbase + l0 + ll) * DINNER + d0 + dd;
            yh[g] = __float2half_rn(y_s[ll][dd] * sz_s[buf][ll][dd]);
        }
        __syncthreads();
        buf ^= 1;
    }
}

// ---------------- launch ----------------
extern "C" void kernel_launch(void* const* d_in, const int* in_sizes, int n_in,
                              void* d_out, int out_size)
{
    (void)in_sizes; (void)n_in; (void)out_size;
    const float* x       = (const float*)d_in[0];
    const float* in_proj = (const float*)d_in[1];
    const float* conv_w  = (const float*)d_in[2];
    const float* conv_b  = (const float*)d_in[3];
    const float* dt_w    = (const float*)d_in[4];
    const float* dt_b    = (const float*)d_in[5];
    const float* A_log   = (const float*)d_in[6];
    const float* Dp      = (const float*)d_in[7];
    const float* B_w     = (const float*)d_in[8];
    const float* C_w     = (const float*)d_in[9];
    const float* out_w   = (const float*)d_in[10];
    float* out = (float*)d_out;

    auto ga = [](const void* sym) { void* p; cudaGetSymbolAddress(&p, sym); return p; };
    __half* xh  = (__half*)ga(g_xh);
    __half* wzh = (__half*)ga(g_wzh);
    __half* wth = (__half*)ga(g_wth);
    __half* Ph  = (__half*)ga(g_Ph);
    float*  Mf  = (float*)ga(g_Mf);
    __half* Mbh = (__half*)ga(g_Mbh);  __half* Mbl = (__half*)ga(g_Mbl);
    __half* dwh = (__half*)ga(g_dwh);
    __half* owh = (__half*)ga(g_owh);
    float* u  = (float*)ga(g_u);
    __half* uh = (__half*)ga(g_uh);
    float* s  = (float*)ga(g_s);
    float* dtp = (float*)ga(g_dt);
    __half* yh = (__half*)ga(g_yh);
    float* Bm = (float*)ga(g_Bm);
    float* Cm = (float*)ga(g_Cm);

    cudaFuncSetAttribute(tgemm<0,0,false,false,1>, cudaFuncAttributeMaxDynamicSharedMemorySize, GSMEM1);
    cudaFuncSetAttribute(tgemm<0,1,false,false,1>, cudaFuncAttributeMaxDynamicSharedMemorySize, GSMEM1);
    cudaFuncSetAttribute(tgemm<1,0,true,true,2>,   cudaFuncAttributeMaxDynamicSharedMemorySize, GSMEM2);
    cudaFuncSetAttribute(tgemm<0,2,true,false,1>,  cudaFuncAttributeMaxDynamicSharedMemorySize, GSMEM1);

    // conversions (hi-only where the lo slice is dead)
    splith_k<<<4096, 256>>>(x, xh);                                      // x
    splith_k<<<2048, 256>>>(in_proj + (size_t)DINNER * DMODEL, wzh);     // Wz
    tsplit_k<<<dim3(32, 64), 256>>>(in_proj, wth);                       // WxcT
    splith_k<<<4096, 256>>>(dt_w, dwh);                                  // dt_w
    splith_k<<<2048, 256>>>(out_w, owh);                                 // out_w
    pack_split_k<<<16384, 256>>>(conv_w);                                // conv taps

    // fold: M_k = P_k @ Wxc   (M=8192, N=1024, K=2048), 1-pass
    tgemm<0,0,false,false,1><<<dim3(8, 64), 256, GSMEM1>>>(
        Ph, wth, nullptr, nullptr, Mf, nullptr, 8192, 1024, 2048);
    mrelayout_k<<<8192, 256>>>(Mf);

    // silu(z) = silu(x @ Wz^T), 1-pass
    tgemm<0,1,false,false,1><<<dim3(16, 32), 256, GSMEM1>>>(
        xh, wzh, nullptr, nullptr, s, nullptr, NTOK, DINNER, DMODEL);

    // u = conv fold (shifted K=4096) + conv_b; emits f16 hi of u; 2-pass
    tgemm<1,0,true,true,2><<<dim3(16, 32), 256, GSMEM2>>>(
        xh, Mbh, Mbl, conv_b, u, uh, NTOK, DINNER, 4 * DMODEL);

    // dt = clip(sigmoid(u @ dt_w^T + dt_b)), 1-pass
    tgemm<0,2,true,false,1><<<dim3(16, 32), 256, GSMEM1>>>(
        uh, dwh, nullptr, dt_b, dtp, nullptr, NTOK, DINNER, DINNER);

    // B/C projections
    bc_gemm<<<NTOK / 32, 256>>>(u, B_w, C_w);

    // selective scan -> yh (f16)
    scan_k<<<128, 512>>>(u, dtp, Bm, Cm, A_log, Dp, s, yh);

    // out = y @ out_w^T, 1-pass
    tgemm<0,0,false,false,1><<<dim3(8, 32), 256, GSMEM1>>>(
        yh, owh, nullptr, nullptr, out, nullptr, NTOK, DMODEL, DINNER);
}

// round 8
// speedup vs baseline: 2.1268x; 1.2251x over previous
#include <cuda_runtime.h>
#include <cuda_fp16.h>
#include <math.h>
#include <stdint.h>

#define DMODEL 1024
#define DINNER 2048
#define DSTATE 16
#define SEQLEN 2048
#define NTOK   4096   /* BATCH * SEQLEN */

// ---------------- scratch (device globals; no runtime allocation) ----------------
__device__ __half g_xh [NTOK * DMODEL];
__device__ __half g_wzh[DINNER * DMODEL];
__device__ __half g_wth[DMODEL * DINNER];     // WxcT hi
__device__ __half g_Ph [4u * DINNER * DINNER];
__device__ __half g_Mbh[DINNER * 4 * DMODEL]; // folded conv weights, conv layout
__device__ __half g_dwh[DINNER * DINNER];
__device__ __half g_owh[DMODEL * DINNER];
__device__ float  g_u  [NTOK * DINNER];
__device__ __half g_uh [NTOK * DINNER];
__device__ float  g_s  [NTOK * DINNER];       // silu(z)
__device__ float  g_dt [NTOK * DINNER];
__device__ __half g_yh [NTOK * DINNER];
__device__ float  g_Bm [NTOK * DSTATE], g_Cm [NTOK * DSTATE];

// ---------------- helpers ----------------
__device__ __forceinline__ uint32_t smem_u32(const void* p) {
    uint32_t a;
    asm("{ .reg .u64 t; cvta.to.shared.u64 t, %1; cvt.u32.u64 %0, t; }" : "=r"(a) : "l"(p));
    return a;
}

#define LDSM4(r, a) asm volatile( \
    "ldmatrix.sync.aligned.m8n8.x4.shared.b16 {%0,%1,%2,%3}, [%4];" \
    : "=r"((r)[0]), "=r"((r)[1]), "=r"((r)[2]), "=r"((r)[3]) : "r"(a))

#define MMAF32(c, a, b0, b1) asm volatile( \
    "mma.sync.aligned.m16n8k16.row.col.f32.f16.f16.f32 " \
    "{%0,%1,%2,%3},{%4,%5,%6,%7},{%8,%9},{%0,%1,%2,%3};" \
    : "+f"((c)[0]), "+f"((c)[1]), "+f"((c)[2]), "+f"((c)[3]) \
    : "r"((a)[0]), "r"((a)[1]), "r"((a)[2]), "r"((a)[3]), "r"(b0), "r"(b1))

#define CPA(dst, src, sz) asm volatile( \
    "cp.async.cg.shared.global [%0], [%1], 16, %2;" :: "r"(dst), "l"(src), "r"(sz))

// ---------------- conversion kernels ----------------
// hi-only split
__global__ void splith_k(const float* __restrict__ in, __half* __restrict__ h) {
    int i = blockIdx.x * 256 + threadIdx.x;
    float4 v = reinterpret_cast<const float4*>(in)[i];
    reinterpret_cast<__half2*>(h)[2 * i]     = __floats2half2_rn(v.x, v.y);
    reinterpret_cast<__half2*>(h)[2 * i + 1] = __floats2half2_rn(v.z, v.w);
}

// transpose hi: in_proj rows 0..2047 ([2048,1024]) -> WxcT [1024,2048]
__global__ void tsplit_k(const float* __restrict__ w, __half* __restrict__ th) {
    __shared__ float t[32][33];
    int j0 = blockIdx.x * 32, i0 = blockIdx.y * 32;
    int tx = threadIdx.x & 31, ty4 = threadIdx.x >> 5;
#pragma unroll
    for (int s = 0; s < 4; s++) {
        int ty = ty4 + s * 8;
        t[ty][tx] = w[(size_t)(i0 + ty) * DMODEL + j0 + tx];
    }
    __syncthreads();
#pragma unroll
    for (int s = 0; s < 4; s++) {
        int ty = ty4 + s * 8;
        th[(size_t)(j0 + ty) * DINNER + i0 + tx] = __float2half_rn(t[tx][ty]);
    }
}

// conv_w [d][i][4] -> P_hi [tap][d][i]
__global__ void pack_split_k(const float* __restrict__ cw) {
    int g = blockIdx.x * 256 + threadIdx.x;
    float4 v = reinterpret_cast<const float4*>(cw)[g];
    float vv[4] = {v.x, v.y, v.z, v.w};
#pragma unroll
    for (int t = 0; t < 4; t++)
        g_Ph[(size_t)t * 4194304u + g] = __float2half_rn(vv[t]);
}

// ---------------- HMMA 1-pass GEMM: D = A @ B^T (both operands K-major) ----------------
// MODE 0: normal. MODE 1: conv-fold (A = x with per-1024-K-chunk row shift tap-3).
// MODE 2: fold-output remap — write f16 only, to Mb[d][tap*1024+col] with m=tap*2048+d.
// EPI 0: none, 1: silu, 2: sigmoid+clip. HASB: +bias[n]. HILO: also write f16 hi of result.
#define KTILE   64
#define PITCH_B 144                // 64 halves data + 16B pad -> conflict-free ldmatrix
#define MATB    (128 * PITCH_B)    // 18432 B per matrix tile
#define NSTAGE  3
#define GSMEM   (NSTAGE * 2 * MATB)   // 110592 B (Ah, Bh) -> 2 CTAs/SM

template<int MODE, int EPI, bool HASB, bool HILO>
__global__ __launch_bounds__(256, 2)
void tgemm(const __half* __restrict__ Ah, const __half* __restrict__ Bh,
           const float* __restrict__ bias, float* __restrict__ out,
           __half* __restrict__ oh,
           int M, int N, int K)
{
    extern __shared__ char sm_[];
    const int tid = threadIdx.x, lane = tid & 31, wid = tid >> 5;
    const int m0 = blockIdx.y * 128, n0 = blockIdx.x * 128;
    const uint32_t sb = smem_u32(sm_);

    const int wm = wid >> 2, wn = wid & 3;          // warp tile: 64(m) x 32(n)
    const int lr = lane & 15, lc8 = (lane >> 4) * 8;
    const uint32_t aoffH = (uint32_t)((wm * 64 + lr) * PITCH_B + lc8 * 2);
    const uint32_t boffH = (uint32_t)(MATB + (wn * 32 + lr) * PITCH_B + lc8 * 2);

    float acc[4][4][4] = {};

    // stage loader: 8 x 16B chunks per thread (Ah + Bh)
    auto ldst = [&](int kt) {
        const uint32_t st = sb + (kt % NSTAGE) * (2 * MATB);
        const int kb = kt * KTILE;
#pragma unroll
        for (int q = 0; q < 8; q++) {
            int cid = q * 256 + tid;
            int mat = cid >> 10, w = cid & 1023;
            int row = w >> 3, c = w & 7;
            uint32_t dst = st + mat * MATB + row * PITCH_B + c * 16;
            const __half* src;
            uint32_t sz = 16;
            if (mat == 0) {
                if (MODE == 1) {
                    int tap = kb >> 10, jb = kb & 1023, rg = m0 + row;
                    if (((rg & (SEQLEN - 1)) + tap - 3) < 0) { sz = 0; src = Ah; }
                    else src = Ah + (size_t)(rg + tap - 3) * DMODEL + jb + c * 8;
                } else {
                    src = Ah + (size_t)(m0 + row) * K + kb + c * 8;
                }
            } else {
                src = Bh + (size_t)(n0 + row) * K + kb + c * 8;
            }
            CPA(dst, src, sz);
        }
        asm volatile("cp.async.commit_group;" ::: "memory");
    };

    auto comp = [&](int s) {
        const uint32_t st = sb + s * (2 * MATB);
#pragma unroll
        for (int kk = 0; kk < KTILE / 16; kk++) {
            const uint32_t ko = kk * 32;            // 16 halves = 32 bytes
            uint32_t ah[4][4], bhf[2][4];
#pragma unroll
            for (int mt = 0; mt < 4; mt++) LDSM4(ah[mt], st + aoffH + mt * 16 * PITCH_B + ko);
#pragma unroll
            for (int np = 0; np < 2; np++) LDSM4(bhf[np], st + boffH + np * 16 * PITCH_B + ko);
#pragma unroll
            for (int mt = 0; mt < 4; mt++)
#pragma unroll
                for (int nt = 0; nt < 4; nt++)
                    MMAF32(acc[mt][nt], ah[mt], bhf[nt >> 1][nt & 1], bhf[nt >> 1][2 + (nt & 1)]);
        }
    };

    const int nk = K / KTILE;
    ldst(0);
    ldst(1);
    for (int kt = 0; kt < nk; kt++) {
        if (kt + 1 < nk) asm volatile("cp.async.wait_group 1;" ::: "memory");
        else             asm volatile("cp.async.wait_group 0;" ::: "memory");
        __syncthreads();
        if (kt + 2 < nk) ldst(kt + 2);
        comp(kt % NSTAGE);
    }

    // epilogue from register accumulators
    const int g = lane >> 2, tg = lane & 3;
#pragma unroll
    for (int mt = 0; mt < 4; mt++) {
#pragma unroll
        for (int nt = 0; nt < 4; nt++) {
            const int col = n0 + wn * 32 + nt * 8 + tg * 2;
            float b0 = 0.f, b1 = 0.f;
            if (HASB) { b0 = bias[col]; b1 = bias[col + 1]; }
#pragma unroll
            for (int h = 0; h < 2; h++) {
                const int r = m0 + wm * 64 + mt * 16 + g + h * 8;
                float v0 = acc[mt][nt][2 * h + 0] + b0;
                float v1 = acc[mt][nt][2 * h + 1] + b1;
                if (EPI == 1) {
                    v0 = v0 / (1.f + __expf(-v0));
                    v1 = v1 / (1.f + __expf(-v1));
                } else if (EPI == 2) {
                    v0 = fminf(fmaxf(1.f / (1.f + __expf(-v0)), 1e-4f), 1.f);
                    v1 = fminf(fmaxf(1.f / (1.f + __expf(-v1)), 1e-4f), 1.f);
                }
                if (MODE == 2) {
                    // fold remap: m = tap*2048 + d  ->  Mb[d][tap*1024 + col], f16 only
                    size_t dst = (size_t)(r & 2047) * 4096 + (size_t)(r >> 11) * 1024 + col;
                    *reinterpret_cast<__half2*>(oh + dst) = __floats2half2_rn(v0, v1);
                } else {
                    *reinterpret_cast<float2*>(out + (size_t)r * N + col) = make_float2(v0, v1);
                    if (HILO)
                        *reinterpret_cast<__half2*>(oh + (size_t)r * N + col) = __floats2half2_rn(v0, v1);
                }
            }
        }
    }
}

// ---------------- small B/C projection GEMM ----------------
__global__ __launch_bounds__(256)
void bc_gemm(const float* __restrict__ u, const float* __restrict__ Bw,
             const float* __restrict__ Cw)
{
    __shared__ float us[32][65];
    __shared__ float ws[32][65];
    const int tid  = threadIdx.x;
    const int row0 = blockIdx.x * 32;
    const int c  = tid & 31;
    const int rq = tid >> 5;
    float acc[4] = {0.f, 0.f, 0.f, 0.f};

    for (int kt = 0; kt < DINNER; kt += 64) {
        __syncthreads();
#pragma unroll
        for (int s = 0; s < 8; s++) {
            int e = tid + s * 256;
            int r = e >> 6, k = e & 63;
            us[r][k] = u[(size_t)(row0 + r) * DINNER + kt + k];
            ws[r][k] = (r < 16) ? Bw[r * DINNER + kt + k]
                                : Cw[(r - 16) * DINNER + kt + k];
        }
        __syncthreads();
#pragma unroll 8
        for (int k = 0; k < 64; k++) {
            float wv = ws[c][k];
#pragma unroll
            for (int i = 0; i < 4; i++)
                acc[i] = fmaf(us[rq * 4 + i][k], wv, acc[i]);
        }
    }
#pragma unroll
    for (int i = 0; i < 4; i++) {
        int row = row0 + rq * 4 + i;
        if (c < 16) g_Bm[(size_t)row * DSTATE + c]        = acc[i];
        else        g_Cm[(size_t)row * DSTATE + (c - 16)] = acc[i];
    }
}

// ---------------- selective scan (emits f16 hi of y for the out GEMM) ----------------
__global__ __launch_bounds__(512)
void scan_k(const float* __restrict__ u, const float* __restrict__ dt,
            const float* __restrict__ Bm, const float* __restrict__ Cm,
            const float* __restrict__ Alog, const float* __restrict__ Dp,
            const float* __restrict__ sz, __half* __restrict__ yh)
{
    const int tid = threadIdx.x;
    const int b   = blockIdx.x >> 6;
    const int d0  = (blockIdx.x & 63) * 32;
    const int dl  = tid >> 4;
    const int n   = tid & 15;
    const int d   = d0 + dl;
    const float Areg = -expf(Alog[d * DSTATE + n]);
    const float Dreg = Dp[d];
    const size_t rowbase = (size_t)b * SEQLEN;
    float state = 0.f;

    __shared__ float dt_s[2][32][32];
    __shared__ float u_s [2][32][32];
    __shared__ float sz_s[2][32][32];
    __shared__ float B_s [2][32][16];
    __shared__ float C_s [2][32][16];
    __shared__ float y_s [32][32];

    auto stage = [&](int buf, int l0) {
#pragma unroll
        for (int s = 0; s < 2; s++) {
            int e = tid + s * 512;
            int ll = e >> 5, dd = e & 31;
            size_t g = (rowbase + l0 + ll) * DINNER + d0 + dd;
            dt_s[buf][ll][dd] = dt[g];
            u_s [buf][ll][dd] = u[g];
            sz_s[buf][ll][dd] = sz[g];
        }
        {
            int ll = tid >> 4, nn = tid & 15;
            size_t g = (rowbase + l0 + ll) * DSTATE + nn;
            B_s[buf][ll][nn] = Bm[g];
            C_s[buf][ll][nn] = Cm[g];
        }
    };

    stage(0, 0);
    __syncthreads();
    int buf = 0;
    for (int t = 0; t < SEQLEN / 32; t++) {
        const int l0 = t * 32;
        if (t + 1 < SEQLEN / 32) stage(buf ^ 1, l0 + 32);
#pragma unroll 4
        for (int ll = 0; ll < 32; ll++) {
            float dtv = dt_s[buf][ll][dl];
            float uv  = u_s [buf][ll][dl];
            float Bn  = B_s [buf][ll][n];
            float Cn  = C_s [buf][ll][n];
            float arg = fminf(fmaxf(dtv * Areg, -5.f), 5.f);
            float dA  = __expf(arg);
            float dB  = dtv * uv * Bn;
            state = fmaf(dA, state, dB + 1e-6f);
            float v = state * Cn;
            v += __shfl_xor_sync(0xffffffffu, v, 8);
            v += __shfl_xor_sync(0xffffffffu, v, 4);
            v += __shfl_xor_sync(0xffffffffu, v, 2);
            v += __shfl_xor_sync(0xffffffffu, v, 1);
            if (n == 0) y_s[ll][dl] = v + Dreg * uv;
        }
        __syncthreads();
#pragma unroll
        for (int s = 0; s < 2; s++) {
            int e = tid + s * 512;
            int ll = e >> 5, dd = e & 31;
            size_t g = (rowbase + l0 + ll) * DINNER + d0 + dd;
            yh[g] = __float2half_rn(y_s[ll][dd] * sz_s[buf][ll][dd]);
        }
        __syncthreads();
        buf ^= 1;
    }
}

// ---------------- launch ----------------
extern "C" void kernel_launch(void* const* d_in, const int* in_sizes, int n_in,
                              void* d_out, int out_size)
{
    (void)in_sizes; (void)n_in; (void)out_size;
    const float* x       = (const float*)d_in[0];
    const float* in_proj = (const float*)d_in[1];
    const float* conv_w  = (const float*)d_in[2];
    const float* conv_b  = (const float*)d_in[3];
    const float* dt_w    = (const float*)d_in[4];
    const float* dt_b    = (const float*)d_in[5];
    const float* A_log   = (const float*)d_in[6];
    const float* Dp      = (const float*)d_in[7];
    const float* B_w     = (const float*)d_in[8];
    const float* C_w     = (const float*)d_in[9];
    const float* out_w   = (const float*)d_in[10];
    float* out = (float*)d_out;

    auto ga = [](const void* sym) { void* p; cudaGetSymbolAddress(&p, sym); return p; };
    __half* xh  = (__half*)ga(g_xh);
    __half* wzh = (__half*)ga(g_wzh);
    __half* wth = (__half*)ga(g_wth);
    __half* Ph  = (__half*)ga(g_Ph);
    __half* Mbh = (__half*)ga(g_Mbh);
    __half* dwh = (__half*)ga(g_dwh);
    __half* owh = (__half*)ga(g_owh);
    float* u  = (float*)ga(g_u);
    __half* uh = (__half*)ga(g_uh);
    float* s  = (float*)ga(g_s);
    float* dtp = (float*)ga(g_dt);
    __half* yh = (__half*)ga(g_yh);
    float* Bm = (float*)ga(g_Bm);
    float* Cm = (float*)ga(g_Cm);

    cudaFuncSetAttribute(tgemm<2,0,false,true>,  cudaFuncAttributeMaxDynamicSharedMemorySize, GSMEM);
    cudaFuncSetAttribute(tgemm<0,1,false,false>, cudaFuncAttributeMaxDynamicSharedMemorySize, GSMEM);
    cudaFuncSetAttribute(tgemm<1,0,true,true>,   cudaFuncAttributeMaxDynamicSharedMemorySize, GSMEM);
    cudaFuncSetAttribute(tgemm<0,2,true,false>,  cudaFuncAttributeMaxDynamicSharedMemorySize, GSMEM);
    cudaFuncSetAttribute(tgemm<0,0,false,false>, cudaFuncAttributeMaxDynamicSharedMemorySize, GSMEM);

    // conversions (all hi-only)
    splith_k<<<4096, 256>>>(x, xh);                                      // x
    splith_k<<<2048, 256>>>(in_proj + (size_t)DINNER * DMODEL, wzh);     // Wz
    tsplit_k<<<dim3(32, 64), 256>>>(in_proj, wth);                       // WxcT
    splith_k<<<4096, 256>>>(dt_w, dwh);                                  // dt_w
    splith_k<<<2048, 256>>>(out_w, owh);                                 // out_w
    pack_split_k<<<16384, 256>>>(conv_w);                                // conv taps

    // fold: M_k = P_k @ Wxc (M=8192, N=1024, K=2048) -> writes Mbh directly (remap)
    tgemm<2,0,false,true><<<dim3(8, 64), 256, GSMEM>>>(
        Ph, wth, nullptr, nullptr, Mbh, 8192, 1024, 2048);

    // silu(z) = silu(x @ Wz^T)
    tgemm<0,1,false,false><<<dim3(16, 32), 256, GSMEM>>>(
        xh, wzh, nullptr, s, nullptr, NTOK, DINNER, DMODEL);

    // u = conv fold (shifted K=4096) + conv_b; emits f16 hi of u
    tgemm<1,0,true,true><<<dim3(16, 32), 256, GSMEM>>>(
        xh, Mbh, conv_b, u, uh, NTOK, DINNER, 4 * DMODEL);

    // dt = clip(sigmoid(u @ dt_w^T + dt_b))
    tgemm<0,2,true,false><<<dim3(16, 32), 256, GSMEM>>>(
        uh, dwh, dt_b, dtp, nullptr, NTOK, DINNER, DINNER);

    // B/C projections
    bc_gemm<<<NTOK / 32, 256>>>(u, B_w, C_w);

    // selective scan -> yh (f16)
    scan_k<<<128, 512>>>(u, dtp, Bm, Cm, A_log, Dp, s, yh);

    // out = y @ out_w^T
    tgemm<0,0,false,false><<<dim3(8, 32), 256, GSMEM>>>(
        yh, owh, nullptr, out, nullptr, NTOK, DMODEL, DINNER);
}